// round 8
// baseline (speedup 1.0000x reference)
#include <cuda_runtime.h>
#include <math.h>
#include <stdint.h>

#define DIMC   1024
#define NB     2
#define NSEQ   2048
#define NHEADS 16
#define NEFF   8
#define HDIM   64
#define HD2    128
#define MTOT   (NB*NSEQ)          // 4096
#define L2E    1.4426950408889634f

// ---------------- scratch (device globals; no allocations allowed) ----------
// NOTE: all tf32 operand tensors use k-dim pair-interleaved layout within each
// 8-block: logical col c stored at (c&~7) | ((c&3)<<1) | ((c>>2)&1).
__device__ float g_lambda;
__device__ float g_xr[MTOT*DIMC];              // tf32-rounded x (interleaved k)
__device__ float g_wr[4][DIMC*DIMC];           // tf32-rounded W (interleaved k)
__device__ float g_q[NB*NHEADS*NSEQ*HDIM];     // [b,h,n,hd-interleaved] (pre-scaled)
__device__ float g_k[NB*NHEADS*NSEQ*HDIM];     // [b,h,n,hd-interleaved]
__device__ float g_v[NB*NEFF*HD2*NSEQ];        // TRANSPOSED: [b,e,d,n] raw fp32
__device__ float g_attn[NB*NHEADS*NSEQ*HD2];   // per-head flash output (natural d)
__device__ float g_comb[MTOT*DIMC];            // combined+normed (interleaved k)

// ==================== helpers ======================
__device__ __forceinline__ uint32_t smem_u32(const void* p) {
    uint32_t a;
    asm("{ .reg .u64 t; cvta.to.shared.u64 t, %1; cvt.u32.u64 %0, t; }" : "=r"(a) : "l"(p));
    return a;
}
__device__ __forceinline__ float f2tf(float x) {   // round-to-nearest tf32
    uint32_t r;
    asm("cvt.rna.tf32.f32 %0, %1;" : "=r"(r) : "f"(x));
    return __uint_as_float(r);
}
__device__ __forceinline__ uint32_t fb(float x) { return __float_as_uint(x); }

// m16n8k8 tf32 mma: D += A(row) * B(col)
__device__ __forceinline__ void mma8(float* d, const uint32_t* a, uint32_t b0, uint32_t b1) {
    asm volatile("mma.sync.aligned.m16n8k8.row.col.f32.tf32.tf32.f32 "
                 "{%0,%1,%2,%3}, {%4,%5,%6,%7}, {%8,%9}, {%0,%1,%2,%3};"
                 : "+f"(d[0]), "+f"(d[1]), "+f"(d[2]), "+f"(d[3])
                 : "r"(a[0]), "r"(a[1]), "r"(a[2]), "r"(a[3]), "r"(b0), "r"(b1));
}

#define CP_ASYNC16(dst, src) \
    asm volatile("cp.async.cg.shared.global [%0], [%1], 16;" :: "r"(dst), "l"(src) : "memory")
#define CP_COMMIT() asm volatile("cp.async.commit_group;" ::: "memory")
#define CP_WAIT1()  asm volatile("cp.async.wait_group 1;" ::: "memory")
#define CP_WAIT2()  asm volatile("cp.async.wait_group 2;" ::: "memory")

// ---------------- tf32 pre-round + k-pair interleave ------------------------
__global__ __launch_bounds__(256) void round_kernel(const float* __restrict__ src,
                                                    float* __restrict__ dst)
{
    int i = (blockIdx.x * 256 + threadIdx.x) * 4;
    float4 v = *(const float4*)(src + i);
    int b8  = i & ~7;
    int off = (i & 4) ? 1 : 0;
    dst[b8 + off + 0] = f2tf(v.x);
    dst[b8 + off + 2] = f2tf(v.y);
    dst[b8 + off + 4] = f2tf(v.z);
    dst[b8 + off + 6] = f2tf(v.w);
}

// ---------------- lambda = exp(lq1.lk1) - exp(lq2.lk2) + 0.8 ----------------
__global__ void lambda_kernel(const float* __restrict__ lq1, const float* __restrict__ lk1,
                              const float* __restrict__ lq2, const float* __restrict__ lk2)
{
    int t = threadIdx.x;
    float s1 = 0.f, s2 = 0.f;
    for (int i = t; i < HDIM; i += 32) {
        s1 += lq1[i] * lk1[i];
        s2 += lq2[i] * lk2[i];
    }
    #pragma unroll
    for (int off = 16; off > 0; off >>= 1) {
        s1 += __shfl_xor_sync(0xffffffffu, s1, off);
        s2 += __shfl_xor_sync(0xffffffffu, s2, off);
    }
    if (t == 0) g_lambda = expf(s1) - expf(s2) + 0.8f;
}

// ============ tf32 mma.sync GEMM NT, 3-stage cp.async pipeline ==============
// 256 threads (8 warps), CTA 128x128, warp 32x64 (2m x 8n atoms), K-chunk 32.
// Operands pre-interleaved -> every frag load is an LDS.64.
#define SSTR (128*36)      // floats per matrix per stage

__global__ __launch_bounds__(256, 2) void gemm_mma_kernel(const float* __restrict__ A,
                                                          const float* __restrict__ W,
                                                          const float* __restrict__ bias,
                                                          float* __restrict__ outp, int mode)
{
    extern __shared__ float smem[];
    uint32_t sbase = smem_u32(smem);

    const float* Ap = (mode == 3) ? g_comb : A;
    int m0 = blockIdx.y * 128;
    int n0 = blockIdx.x * 128;
    int tid = threadIdx.x, wid = tid >> 5, lane = tid & 31;
    int wm = wid >> 1, wn = wid & 1;
    int g = lane >> 2, tg = lane & 3;

    int lrow = tid >> 3;                  // 0..31 (row step 32 over i)
    int lc4  = (tid & 7) * 4;             // 0..28

    float acc[2][8][4];
    #pragma unroll
    for (int mi = 0; mi < 2; mi++)
        #pragma unroll
        for (int ni = 0; ni < 8; ni++)
            #pragma unroll
            for (int j = 0; j < 4; j++) acc[mi][ni][j] = 0.f;

    #define GEMM_ISSUE(c, st) do { \
        uint32_t as = sbase + (uint32_t)((st) * 2 * SSTR) * 4u; \
        uint32_t bs = as + (uint32_t)SSTR * 4u; \
        const float* ag = Ap + (size_t)m0 * DIMC + (c) * 32; \
        const float* bg = W  + (size_t)n0 * DIMC + (c) * 32; \
        _Pragma("unroll") \
        for (int i = 0; i < 4; i++) { \
            int row = lrow + i * 32; \
            CP_ASYNC16(as + (uint32_t)(row * 36 + lc4) * 4u, ag + (size_t)row * DIMC + lc4); \
            CP_ASYNC16(bs + (uint32_t)(row * 36 + lc4) * 4u, bg + (size_t)row * DIMC + lc4); \
        } \
    } while (0)

    GEMM_ISSUE(0, 0); CP_COMMIT();
    GEMM_ISSUE(1, 1); CP_COMMIT();

    int st = 0;
    for (int c = 0; c < 32; c++) {
        int st2 = st + 2 >= 3 ? st - 1 : st + 2;
        if (c + 2 < 32) GEMM_ISSUE(c + 2, st2);
        CP_COMMIT();
        CP_WAIT2();
        __syncthreads();

        const float* As = smem + st * 2 * SSTR;
        const float* Bs = As + SSTR;
        #pragma unroll
        for (int kk = 0; kk < 4; kk++) {
            uint32_t a[2][4];
            #pragma unroll
            for (int mi = 0; mi < 2; mi++) {
                const float* r0 = As + (wm * 32 + mi * 16 + g) * 36 + kk * 8 + 2 * tg;
                float2 u = *(const float2*)r0;
                float2 w2 = *(const float2*)(r0 + 8 * 36);
                a[mi][0] = fb(u.x); a[mi][1] = fb(w2.x);
                a[mi][2] = fb(u.y); a[mi][3] = fb(w2.y);
            }
            #pragma unroll
            for (int ni = 0; ni < 8; ni++) {
                float2 b = *(const float2*)(Bs + (wn * 64 + ni * 8 + g) * 36 + kk * 8 + 2 * tg);
                mma8(acc[0][ni], a[0], fb(b.x), fb(b.y));
                mma8(acc[1][ni], a[1], fb(b.x), fb(b.y));
            }
        }
        __syncthreads();
        st = st + 1 >= 3 ? 0 : st + 1;
    }

    // epilogue: scatter with bias
    #pragma unroll
    for (int mi = 0; mi < 2; mi++) {
        int m = m0 + wm * 32 + mi * 16 + g;
        #pragma unroll
        for (int ni = 0; ni < 8; ni++) {
            int n = n0 + wn * 64 + ni * 8 + tg * 2;
            float2 bs2 = *(const float2*)(bias + n);
            #pragma unroll
            for (int half = 0; half < 2; half++) {
                int mm = m + half * 8;
                float x = acc[mi][ni][half * 2 + 0] + bs2.x;
                float y = acc[mi][ni][half * 2 + 1] + bs2.y;
                int b_ = mm >> 11, nn = mm & 2047;
                if (mode == 0) {
                    int h = n >> 6, hd = n & 63;
                    int hdi = (hd & ~7) | ((hd & 3) << 1) | ((hd >> 2) & 1);
                    float* p = g_q + (((size_t)(b_*NHEADS+h))*NSEQ+nn)*HDIM;
                    p[hdi]     = f2tf(x * 0.125f);
                    p[hdi + 2] = f2tf(y * 0.125f);
                } else if (mode == 1) {
                    int h = n >> 6, hd = n & 63;
                    int hdi = (hd & ~7) | ((hd & 3) << 1) | ((hd >> 2) & 1);
                    float* p = g_k + (((size_t)(b_*NHEADS+h))*NSEQ+nn)*HDIM;
                    p[hdi]     = f2tf(x);
                    p[hdi + 2] = f2tf(y);
                } else if (mode == 2) {
                    int e = n >> 7, d2 = n & 127;
                    float* p = g_v + (((size_t)(b_*NEFF+e))*HD2 + d2)*NSEQ + nn;
                    p[0]    = x;       // transposed [d][n]
                    p[NSEQ] = y;
                } else {
                    *(float2*)(outp + (size_t)mm * DIMC + n) = make_float2(x, y);
                }
            }
        }
    }
}

// ---------------- flash attention, tf32 mma.sync, register-P ----------------
// Br=128, Bc=64, 256 threads = 8 warps x 16-row stripes.
// Q frags hoisted to regs; S accumulator reused directly as PV A-operand
// (V transposed => B pairs naturally adjacent). No P shared memory.
__global__ __launch_bounds__(256, 1) void flash_kernel()
{
    extern __shared__ float sm[];
    float* Qs = sm;                     // [128][68]
    float* Ks = Qs + 128 * 68;          // [2][64][68]
    float* Vs = Ks + 2 * 64 * 68;       // [2][128][68]  (transposed tiles [d][n])

    int qt = blockIdx.x;                // 0..15
    int bh = blockIdx.y;                // 0..31
    int b_ = bh >> 4, h = bh & 15, e = h >> 1;

    const float* Qg = g_q + ((size_t)bh * NSEQ + qt * 128) * HDIM;
    const float* Kg = g_k + (size_t)bh * NSEQ * HDIM;
    const float* Vg = g_v + ((size_t)(b_ * NEFF + e)) * HD2 * NSEQ;  // [d][n]

    int tid = threadIdx.x, wid = tid >> 5, lane = tid & 31;
    int g = lane >> 2, tg = lane & 3;
    uint32_t qbase = smem_u32(Qs);
    uint32_t kbase = smem_u32(Ks);
    uint32_t vbase = smem_u32(Vs);

    // ---- prologue: Q (own group), then K0+V0
    #pragma unroll
    for (int i = 0; i < 8; i++) {
        int ch = tid + i * 256;
        int row = ch >> 4, c = (ch & 15) * 4;
        CP_ASYNC16(qbase + (uint32_t)(row * 68 + c) * 4u, Qg + (size_t)row * HDIM + c);
    }
    CP_COMMIT();
    #pragma unroll
    for (int i = 0; i < 4; i++) {
        int ch = tid + i * 256;
        int row = ch >> 4, c = (ch & 15) * 4;
        CP_ASYNC16(kbase + (uint32_t)(row * 68 + c) * 4u, Kg + (size_t)row * HDIM + c);
    }
    #pragma unroll
    for (int i = 0; i < 8; i++) {
        int ch = tid + i * 256;
        int row = ch >> 4, c = (ch & 15) * 4;
        CP_ASYNC16(vbase + (uint32_t)(row * 68 + c) * 4u, Vg + (size_t)row * NSEQ + c);
    }
    CP_COMMIT();
    CP_WAIT1();            // Q ready (K0/V0 may still be in flight)
    __syncthreads();

    // hoist Q fragments (kt-invariant)
    uint32_t qf[8][4];
    #pragma unroll
    for (int kk = 0; kk < 8; kk++) {
        const float* r0 = Qs + (wid * 16 + g) * 68 + kk * 8 + 2 * tg;
        float2 u = *(const float2*)r0;
        float2 v = *(const float2*)(r0 + 8 * 68);
        qf[kk][0] = fb(u.x); qf[kk][1] = fb(v.x);
        qf[kk][2] = fb(u.y); qf[kk][3] = fb(v.y);
    }

    float o[16][4];
    #pragma unroll
    for (int ni = 0; ni < 16; ni++)
        #pragma unroll
        for (int j = 0; j < 4; j++) o[ni][j] = 0.f;
    float mrun[2] = {-1e30f, -1e30f};
    float lrun[2] = {0.f, 0.f};

    for (int kt = 0; kt < 32; kt++) {
        int buf = kt & 1;
        if (kt + 1 < 32) {
            uint32_t kb = kbase + (uint32_t)((buf ^ 1) * 64 * 68) * 4u;
            uint32_t vb = vbase + (uint32_t)((buf ^ 1) * 128 * 68) * 4u;
            #pragma unroll
            for (int i = 0; i < 4; i++) {
                int ch = tid + i * 256;
                int row = ch >> 4, c = (ch & 15) * 4;
                CP_ASYNC16(kb + (uint32_t)(row * 68 + c) * 4u,
                           Kg + (size_t)((kt + 1) * 64 + row) * HDIM + c);
            }
            #pragma unroll
            for (int i = 0; i < 8; i++) {
                int ch = tid + i * 256;
                int row = ch >> 4, c = (ch & 15) * 4;
                CP_ASYNC16(vb + (uint32_t)(row * 68 + c) * 4u,
                           Vg + (size_t)row * NSEQ + (kt + 1) * 64 + c);
            }
        }
        CP_COMMIT();
        CP_WAIT1();
        __syncthreads();

        // ---- S = Q K^T
        const float* Kb = Ks + buf * 64 * 68;
        float s[8][4];
        #pragma unroll
        for (int ni = 0; ni < 8; ni++)
            #pragma unroll
            for (int j = 0; j < 4; j++) s[ni][j] = 0.f;
        #pragma unroll
        for (int kk = 0; kk < 8; kk++) {
            #pragma unroll
            for (int ni = 0; ni < 8; ni++) {
                float2 b = *(const float2*)(Kb + (ni * 8 + g) * 68 + kk * 8 + 2 * tg);
                mma8(s[ni], qf[kk], fb(b.x), fb(b.y));
            }
        }

        // ---- online softmax (half 0: row g; half 1: row g+8)
        #pragma unroll
        for (int half = 0; half < 2; half++) {
            float mx = -1e30f;
            #pragma unroll
            for (int ni = 0; ni < 8; ni++) {
                mx = fmaxf(mx, s[ni][half * 2 + 0]);
                mx = fmaxf(mx, s[ni][half * 2 + 1]);
            }
            mx = fmaxf(mx, __shfl_xor_sync(0xffffffffu, mx, 1));
            mx = fmaxf(mx, __shfl_xor_sync(0xffffffffu, mx, 2));
            float mnew = fmaxf(mrun[half], mx);
            float sum = 0.f;
            #pragma unroll
            for (int ni = 0; ni < 8; ni++) {
                float p0 = exp2f((s[ni][half * 2 + 0] - mnew) * L2E);
                float p1 = exp2f((s[ni][half * 2 + 1] - mnew) * L2E);
                s[ni][half * 2 + 0] = p0;
                s[ni][half * 2 + 1] = p1;
                sum += p0 + p1;
            }
            sum += __shfl_xor_sync(0xffffffffu, sum, 1);
            sum += __shfl_xor_sync(0xffffffffu, sum, 2);
            if (mnew > mrun[half]) {
                float alpha = exp2f((mrun[half] - mnew) * L2E);
                lrun[half] = lrun[half] * alpha + sum;
                mrun[half] = mnew;
                #pragma unroll
                for (int ni = 0; ni < 16; ni++) {
                    o[ni][half * 2 + 0] *= alpha;
                    o[ni][half * 2 + 1] *= alpha;
                }
            } else {
                lrun[half] += sum;
            }
        }

        // round P to tf32 (RNA) in registers
        #pragma unroll
        for (int ni = 0; ni < 8; ni++)
            #pragma unroll
            for (int j = 0; j < 4; j++) s[ni][j] = f2tf(s[ni][j]);

        // ---- O += P V : S-accumulator IS the A-fragment ({c0,c2,c1,c3});
        // V transposed tile => B pair = adjacent float2.
        const float* Vb = Vs + buf * 128 * 68;
        #pragma unroll
        for (int kk = 0; kk < 8; kk++) {
            uint32_t a[4] = { fb(s[kk][0]), fb(s[kk][2]), fb(s[kk][1]), fb(s[kk][3]) };
            #pragma unroll
            for (int ni = 0; ni < 16; ni++) {
                float2 b = *(const float2*)(Vb + (ni * 8 + g) * 68 + kk * 8 + 2 * tg);
                mma8(o[ni], a, fb(b.x), fb(b.y));
            }
        }
        __syncthreads();
    }

    // epilogue
    float* Og = g_attn + ((size_t)bh * NSEQ + qt * 128) * HD2;
    #pragma unroll
    for (int half = 0; half < 2; half++) {
        float inv = 1.f / lrun[half];
        int r = wid * 16 + g + half * 8;
        #pragma unroll
        for (int ni = 0; ni < 16; ni++) {
            *(float2*)(Og + (size_t)r * HD2 + ni * 8 + tg * 2) =
                make_float2(o[ni][half * 2 + 0] * inv,
                            o[ni][half * 2 + 1] * inv);
        }
    }
}

// ---------------- combine: o0 - lam*o1, RMSNorm(128), *w*0.2, interleave ----
__global__ __launch_bounds__(128) void combine_kernel(const float* __restrict__ norm_w)
{
    int idx = blockIdx.x;
    int n   = idx & (NSEQ - 1);
    int be  = idx >> 11;
    int b_  = be >> 3, e = be & 7;
    int d   = threadIdx.x;
    float lam = g_lambda;

    size_t base0 = (((size_t)(b_ * NHEADS + 2 * e    )) * NSEQ + n) * HD2;
    size_t base1 = (((size_t)(b_ * NHEADS + 2 * e + 1)) * NSEQ + n) * HD2;
    float xv = g_attn[base0 + d] - lam * g_attn[base1 + d];

    float ss = xv * xv;
    #pragma unroll
    for (int off = 16; off > 0; off >>= 1)
        ss += __shfl_xor_sync(0xffffffffu, ss, off);
    __shared__ float red[4];
    if ((d & 31) == 0) red[d >> 5] = ss;
    __syncthreads();
    float tot = red[0] + red[1] + red[2] + red[3];
    float rms = rsqrtf(tot * (1.0f / HD2) + 1e-5f);

    int di = (d & ~7) | ((d & 3) << 1) | ((d >> 2) & 1);   // k-pair interleave
    g_comb[((size_t)(b_ * NSEQ + n)) * DIMC + e * HD2 + di] =
        f2tf(xv * rms * norm_w[d] * 0.2f);
}

// ---------------- launch -----------------------------------------------------
extern "C" void kernel_launch(void* const* d_in, const int* in_sizes, int n_in,
                              void* d_out, int out_size)
{
    const float* x      = (const float*)d_in[0];
    const float* Wq     = (const float*)d_in[1];
    const float* bq     = (const float*)d_in[2];
    const float* Wk     = (const float*)d_in[3];
    const float* bk     = (const float*)d_in[4];
    const float* Wv     = (const float*)d_in[5];
    const float* bv     = (const float*)d_in[6];
    const float* Wo     = (const float*)d_in[7];
    const float* bo     = (const float*)d_in[8];
    const float* norm_w = (const float*)d_in[9];
    const float* lq1    = (const float*)d_in[10];
    const float* lk1    = (const float*)d_in[11];
    const float* lq2    = (const float*)d_in[12];
    const float* lk2    = (const float*)d_in[13];
    float* out = (float*)d_out;

    lambda_kernel<<<1, 32>>>(lq1, lk1, lq2, lk2);

    float* xr = nullptr; cudaGetSymbolAddress((void**)&xr, g_xr);
    float* wr = nullptr; cudaGetSymbolAddress((void**)&wr, g_wr);
    round_kernel<<<MTOT * DIMC / 1024, 256>>>(x,  xr);
    round_kernel<<<DIMC * DIMC / 1024, 256>>>(Wq, wr + 0 * DIMC * DIMC);
    round_kernel<<<DIMC * DIMC / 1024, 256>>>(Wk, wr + 1 * DIMC * DIMC);
    round_kernel<<<DIMC * DIMC / 1024, 256>>>(Wv, wr + 2 * DIMC * DIMC);
    round_kernel<<<DIMC * DIMC / 1024, 256>>>(Wo, wr + 3 * DIMC * DIMC);

    int gemm_smem = 3 * 2 * SSTR * (int)sizeof(float);   // 110,592 B
    cudaFuncSetAttribute(gemm_mma_kernel, cudaFuncAttributeMaxDynamicSharedMemorySize, gemm_smem);

    dim3 gg(DIMC / 128, MTOT / 128);   // (8, 32)
    gemm_mma_kernel<<<gg, 256, gemm_smem>>>(xr, wr + 0 * DIMC * DIMC, bq, nullptr, 0);
    gemm_mma_kernel<<<gg, 256, gemm_smem>>>(xr, wr + 1 * DIMC * DIMC, bk, nullptr, 1);
    gemm_mma_kernel<<<gg, 256, gemm_smem>>>(xr, wr + 2 * DIMC * DIMC, bv, nullptr, 2);

    int flash_smem = (128 * 68 + 2 * 64 * 68 + 2 * 128 * 68) * (int)sizeof(float); // 139,264
    cudaFuncSetAttribute(flash_kernel, cudaFuncAttributeMaxDynamicSharedMemorySize, flash_smem);
    flash_kernel<<<dim3(NSEQ / 128, NB * NHEADS), 256, flash_smem>>>();

    combine_kernel<<<NB * NEFF * NSEQ, 128>>>(norm_w);

    gemm_mma_kernel<<<gg, 256, gemm_smem>>>(nullptr, wr + 3 * DIMC * DIMC, bo, out, 3);
}

// round 10
// speedup vs baseline: 1.3374x; 1.3374x over previous
#include <cuda_runtime.h>
#include <math.h>
#include <stdint.h>

#define DIMC   1024
#define NB     2
#define NSEQ   2048
#define NHEADS 16
#define NEFF   8
#define HDIM   64
#define HD2    128
#define MTOT   (NB*NSEQ)          // 4096
#define L2E    1.4426950408889634f

// ---------------- scratch (device globals; no allocations allowed) ----------
__device__ float g_lambda;
__device__ float g_xr[MTOT*DIMC];              // tf32-rounded x
__device__ float g_wr[4][DIMC*DIMC];           // tf32-rounded Wq,Wk,Wv,Wo
__device__ float g_q[NB*NHEADS*NSEQ*HDIM];     // [b,h,n,hd] (pre-scaled, tf32-rounded)
__device__ float g_k[NB*NHEADS*NSEQ*HDIM];     // [b,h,n,hd] (tf32-rounded)
__device__ float g_v[NB*NEFF*NSEQ*HD2];        // [b,e,n,128] raw fp32 (natural)
__device__ float g_attn[NB*NHEADS*NSEQ*HD2];   // per-head flash output
__device__ float g_comb[MTOT*DIMC];            // combined+normed (tf32-rounded)

// ==================== helpers ======================
__device__ __forceinline__ uint32_t smem_u32(const void* p) {
    uint32_t a;
    asm("{ .reg .u64 t; cvta.to.shared.u64 t, %1; cvt.u32.u64 %0, t; }" : "=r"(a) : "l"(p));
    return a;
}
__device__ __forceinline__ float f2tf(float x) {   // round-to-nearest tf32
    uint32_t r;
    asm("cvt.rna.tf32.f32 %0, %1;" : "=r"(r) : "f"(x));
    return __uint_as_float(r);
}
__device__ __forceinline__ uint32_t fb(float x) { return __float_as_uint(x); }

// m16n8k8 tf32 mma: D += A(row) * B(col)
__device__ __forceinline__ void mma8(float* d, const uint32_t* a, uint32_t b0, uint32_t b1) {
    asm volatile("mma.sync.aligned.m16n8k8.row.col.f32.tf32.tf32.f32 "
                 "{%0,%1,%2,%3}, {%4,%5,%6,%7}, {%8,%9}, {%0,%1,%2,%3};"
                 : "+f"(d[0]), "+f"(d[1]), "+f"(d[2]), "+f"(d[3])
                 : "r"(a[0]), "r"(a[1]), "r"(a[2]), "r"(a[3]), "r"(b0), "r"(b1));
}

#define CP_ASYNC16(dst, src) \
    asm volatile("cp.async.cg.shared.global [%0], [%1], 16;" :: "r"(dst), "l"(src) : "memory")
#define CP_COMMIT() asm volatile("cp.async.commit_group;" ::: "memory")
#define CP_WAIT1()  asm volatile("cp.async.wait_group 1;" ::: "memory")
#define CP_WAIT2()  asm volatile("cp.async.wait_group 2;" ::: "memory")

// ---------------- tf32 pre-round: dst[i] = rna_tf32(src[i]) ----------------
__global__ __launch_bounds__(256) void round_kernel(const float* __restrict__ src,
                                                    float* __restrict__ dst)
{
    int i = (blockIdx.x * 256 + threadIdx.x) * 4;
    float4 v = *(const float4*)(src + i);
    v.x = f2tf(v.x); v.y = f2tf(v.y); v.z = f2tf(v.z); v.w = f2tf(v.w);
    *(float4*)(dst + i) = v;
}

// ---------------- lambda = exp(lq1.lk1) - exp(lq2.lk2) + 0.8 ----------------
__global__ void lambda_kernel(const float* __restrict__ lq1, const float* __restrict__ lk1,
                              const float* __restrict__ lq2, const float* __restrict__ lk2)
{
    int t = threadIdx.x;
    float s1 = 0.f, s2 = 0.f;
    for (int i = t; i < HDIM; i += 32) {
        s1 += lq1[i] * lk1[i];
        s2 += lq2[i] * lk2[i];
    }
    #pragma unroll
    for (int off = 16; off > 0; off >>= 1) {
        s1 += __shfl_xor_sync(0xffffffffu, s1, off);
        s2 += __shfl_xor_sync(0xffffffffu, s2, off);
    }
    if (t == 0) g_lambda = expf(s1) - expf(s2) + 0.8f;
}

// ============ tf32 mma.sync GEMM NT, 3-stage cp.async pipeline ==============
// 256 threads (8 warps), CTA 128x128, warp 32x64 (2m x 8n atoms), K-chunk 32.
// Inputs pre-rounded to tf32 in global. mode 0: g_q(*0.125), 1: g_k, 2: g_v, 3: outp
#define SSTR (128*36)      // floats per matrix per stage

__global__ __launch_bounds__(256, 2) void gemm_mma_kernel(const float* __restrict__ A,
                                                          const float* __restrict__ W,
                                                          const float* __restrict__ bias,
                                                          float* __restrict__ outp, int mode)
{
    extern __shared__ float smem[];
    uint32_t sbase = smem_u32(smem);

    const float* Ap = (mode == 3) ? g_comb : A;
    int m0 = blockIdx.y * 128;
    int n0 = blockIdx.x * 128;
    int tid = threadIdx.x, wid = tid >> 5, lane = tid & 31;
    int wm = wid >> 1, wn = wid & 1;
    int g = lane >> 2, tg = lane & 3;

    int lrow = tid >> 3;                  // 0..31 (row step 32 over i)
    int lc4  = (tid & 7) * 4;             // 0..28

    float acc[2][8][4];
    #pragma unroll
    for (int mi = 0; mi < 2; mi++)
        #pragma unroll
        for (int ni = 0; ni < 8; ni++)
            #pragma unroll
            for (int j = 0; j < 4; j++) acc[mi][ni][j] = 0.f;

    #define GEMM_ISSUE(c, st) do { \
        uint32_t as = sbase + (uint32_t)((st) * 2 * SSTR) * 4u; \
        uint32_t bs = as + (uint32_t)SSTR * 4u; \
        const float* ag = Ap + (size_t)m0 * DIMC + (c) * 32; \
        const float* bg = W  + (size_t)n0 * DIMC + (c) * 32; \
        _Pragma("unroll") \
        for (int i = 0; i < 4; i++) { \
            int row = lrow + i * 32; \
            CP_ASYNC16(as + (uint32_t)(row * 36 + lc4) * 4u, ag + (size_t)row * DIMC + lc4); \
            CP_ASYNC16(bs + (uint32_t)(row * 36 + lc4) * 4u, bg + (size_t)row * DIMC + lc4); \
        } \
    } while (0)

    GEMM_ISSUE(0, 0); CP_COMMIT();
    GEMM_ISSUE(1, 1); CP_COMMIT();

    int st = 0;
    for (int c = 0; c < 32; c++) {
        int st2 = st + 2 >= 3 ? st - 1 : st + 2;
        if (c + 2 < 32) GEMM_ISSUE(c + 2, st2);
        CP_COMMIT();
        CP_WAIT2();
        __syncthreads();

        const float* As = smem + st * 2 * SSTR;
        const float* Bs = As + SSTR;
        #pragma unroll
        for (int kk = 0; kk < 4; kk++) {
            uint32_t a[2][4];
            #pragma unroll
            for (int mi = 0; mi < 2; mi++) {
                const float* base = As + (wm * 32 + mi * 16 + g) * 36 + kk * 8 + tg;
                a[mi][0] = fb(base[0]);
                a[mi][1] = fb(base[8 * 36]);
                a[mi][2] = fb(base[4]);
                a[mi][3] = fb(base[8 * 36 + 4]);
            }
            #pragma unroll
            for (int ni = 0; ni < 8; ni++) {
                const float* bbase = Bs + (wn * 64 + ni * 8 + g) * 36 + kk * 8 + tg;
                uint32_t b0 = fb(bbase[0]);
                uint32_t b1 = fb(bbase[4]);
                mma8(acc[0][ni], a[0], b0, b1);
                mma8(acc[1][ni], a[1], b0, b1);
            }
        }
        __syncthreads();
        st = st + 1 >= 3 ? 0 : st + 1;
    }

    // epilogue: scatter with bias (coalesced float2 stores)
    #pragma unroll
    for (int mi = 0; mi < 2; mi++) {
        int m = m0 + wm * 32 + mi * 16 + g;
        #pragma unroll
        for (int ni = 0; ni < 8; ni++) {
            int n = n0 + wn * 64 + ni * 8 + tg * 2;
            float2 bs2 = *(const float2*)(bias + n);
            #pragma unroll
            for (int half = 0; half < 2; half++) {
                int mm = m + half * 8;
                float x = acc[mi][ni][half * 2 + 0] + bs2.x;
                float y = acc[mi][ni][half * 2 + 1] + bs2.y;
                int b_ = mm >> 11, nn = mm & 2047;
                if (mode == 0) {
                    int h = n >> 6, hd = n & 63;
                    *(float2*)(g_q + (((size_t)(b_*NHEADS+h))*NSEQ+nn)*HDIM + hd) =
                        make_float2(f2tf(x * 0.125f), f2tf(y * 0.125f));
                } else if (mode == 1) {
                    int h = n >> 6, hd = n & 63;
                    *(float2*)(g_k + (((size_t)(b_*NHEADS+h))*NSEQ+nn)*HDIM + hd) =
                        make_float2(f2tf(x), f2tf(y));
                } else if (mode == 2) {
                    int e = n >> 7, d2 = n & 127;
                    *(float2*)(g_v + (((size_t)(b_*NEFF+e))*NSEQ+nn)*HD2 + d2) =
                        make_float2(x, y);
                } else {
                    *(float2*)(outp + (size_t)mm * DIMC + n) = make_float2(x, y);
                }
            }
        }
    }
}

// ---------------- flash attention, tf32 mma.sync, register-P ----------------
// Br=128, Bc=64, 256 threads = 8 warps x 16-row stripes. Natural V layout.
// Q frags hoisted; S accumulator reused as PV A-operand via k-permutation
// pi=[0,2,4,6,1,3,5,7]; B follows pi: keys (2tg, 2tg+1). V row stride 140
// keeps the pi-shifted B loads bank-conflict-free. No P shared memory.
#define VSTR 140

__global__ __launch_bounds__(256, 1) void flash_kernel()
{
    extern __shared__ float sm[];
    float* Qs = sm;                     // [128][68]
    float* Ks = Qs + 128 * 68;          // [2][64][68]
    float* Vs = Ks + 2 * 64 * 68;       // [2][64][VSTR]  natural [key][d]

    int qt = blockIdx.x;                // 0..15
    int bh = blockIdx.y;                // 0..31
    int b_ = bh >> 4, h = bh & 15, e = h >> 1;

    const float* Qg = g_q + ((size_t)bh * NSEQ + qt * 128) * HDIM;
    const float* Kg = g_k + (size_t)bh * NSEQ * HDIM;
    const float* Vg = g_v + ((size_t)(b_ * NEFF + e)) * NSEQ * HD2;

    int tid = threadIdx.x, wid = tid >> 5, lane = tid & 31;
    int g = lane >> 2, tg = lane & 3;
    uint32_t qbase = smem_u32(Qs);
    uint32_t kbase = smem_u32(Ks);
    uint32_t vbase = smem_u32(Vs);

    // ---- prologue: Q (own group), then K0+V0
    #pragma unroll
    for (int i = 0; i < 8; i++) {
        int ch = tid + i * 256;
        int row = ch >> 4, c = (ch & 15) * 4;
        CP_ASYNC16(qbase + (uint32_t)(row * 68 + c) * 4u, Qg + (size_t)row * HDIM + c);
    }
    CP_COMMIT();
    #pragma unroll
    for (int i = 0; i < 4; i++) {
        int ch = tid + i * 256;
        int row = ch >> 4, c = (ch & 15) * 4;
        CP_ASYNC16(kbase + (uint32_t)(row * 68 + c) * 4u, Kg + (size_t)row * HDIM + c);
    }
    #pragma unroll
    for (int i = 0; i < 8; i++) {
        int ch = tid + i * 256;
        int row = ch >> 5, c = (ch & 31) * 4;
        CP_ASYNC16(vbase + (uint32_t)(row * VSTR + c) * 4u, Vg + (size_t)row * HD2 + c);
    }
    CP_COMMIT();
    CP_WAIT1();            // Q ready (K0/V0 may still be in flight)
    __syncthreads();

    // hoist Q fragments (kt-invariant)
    uint32_t qf[8][4];
    #pragma unroll
    for (int kk = 0; kk < 8; kk++) {
        const float* base = Qs + (wid * 16 + g) * 68 + kk * 8 + tg;
        qf[kk][0] = fb(base[0]);
        qf[kk][1] = fb(base[8 * 68]);
        qf[kk][2] = fb(base[4]);
        qf[kk][3] = fb(base[8 * 68 + 4]);
    }

    float o[16][4];
    #pragma unroll
    for (int ni = 0; ni < 16; ni++)
        #pragma unroll
        for (int j = 0; j < 4; j++) o[ni][j] = 0.f;
    float mrun[2] = {-1e30f, -1e30f};
    float lrun[2] = {0.f, 0.f};

    for (int kt = 0; kt < 32; kt++) {
        int buf = kt & 1;
        if (kt + 1 < 32) {
            uint32_t kb = kbase + (uint32_t)((buf ^ 1) * 64 * 68) * 4u;
            uint32_t vb = vbase + (uint32_t)((buf ^ 1) * 64 * VSTR) * 4u;
            #pragma unroll
            for (int i = 0; i < 4; i++) {
                int ch = tid + i * 256;
                int row = ch >> 4, c = (ch & 15) * 4;
                CP_ASYNC16(kb + (uint32_t)(row * 68 + c) * 4u,
                           Kg + (size_t)((kt + 1) * 64 + row) * HDIM + c);
            }
            #pragma unroll
            for (int i = 0; i < 8; i++) {
                int ch = tid + i * 256;
                int row = ch >> 5, c = (ch & 31) * 4;
                CP_ASYNC16(vb + (uint32_t)(row * VSTR + c) * 4u,
                           Vg + (size_t)((kt + 1) * 64 + row) * HD2 + c);
            }
        }
        CP_COMMIT();
        CP_WAIT1();
        __syncthreads();

        // ---- S = Q K^T
        const float* Kb = Ks + buf * 64 * 68;
        float s[8][4];
        #pragma unroll
        for (int ni = 0; ni < 8; ni++)
            #pragma unroll
            for (int j = 0; j < 4; j++) s[ni][j] = 0.f;
        #pragma unroll
        for (int kk = 0; kk < 8; kk++) {
            #pragma unroll
            for (int ni = 0; ni < 8; ni++) {
                const float* bbase = Kb + (ni * 8 + g) * 68 + kk * 8 + tg;
                uint32_t b0 = fb(bbase[0]);
                uint32_t b1 = fb(bbase[4]);
                mma8(s[ni], qf[kk], b0, b1);
            }
        }

        // ---- online softmax (half 0: row g; half 1: row g+8)
        #pragma unroll
        for (int half = 0; half < 2; half++) {
            float mx = -1e30f;
            #pragma unroll
            for (int ni = 0; ni < 8; ni++) {
                mx = fmaxf(mx, s[ni][half * 2 + 0]);
                mx = fmaxf(mx, s[ni][half * 2 + 1]);
            }
            mx = fmaxf(mx, __shfl_xor_sync(0xffffffffu, mx, 1));
            mx = fmaxf(mx, __shfl_xor_sync(0xffffffffu, mx, 2));
            float mnew = fmaxf(mrun[half], mx);
            float sum = 0.f;
            #pragma unroll
            for (int ni = 0; ni < 8; ni++) {
                float p0 = exp2f((s[ni][half * 2 + 0] - mnew) * L2E);
                float p1 = exp2f((s[ni][half * 2 + 1] - mnew) * L2E);
                s[ni][half * 2 + 0] = p0;
                s[ni][half * 2 + 1] = p1;
                sum += p0 + p1;
            }
            sum += __shfl_xor_sync(0xffffffffu, sum, 1);
            sum += __shfl_xor_sync(0xffffffffu, sum, 2);
            if (mnew > mrun[half]) {
                float alpha = exp2f((mrun[half] - mnew) * L2E);
                lrun[half] = lrun[half] * alpha + sum;
                mrun[half] = mnew;
                #pragma unroll
                for (int ni = 0; ni < 16; ni++) {
                    o[ni][half * 2 + 0] *= alpha;
                    o[ni][half * 2 + 1] *= alpha;
                }
            } else {
                lrun[half] += sum;
            }
        }

        // round P to tf32 (RNA) in registers
        #pragma unroll
        for (int ni = 0; ni < 8; ni++)
            #pragma unroll
            for (int j = 0; j < 4; j++) s[ni][j] = f2tf(s[ni][j]);

        // ---- O += P V : S accumulator IS the A-fragment ({c0,c2,c1,c3});
        // k-permutation pi: B loads keys (2tg, 2tg+1) of the kk-block.
        const float* Vb = Vs + buf * 64 * VSTR;
        #pragma unroll
        for (int kk = 0; kk < 8; kk++) {
            uint32_t a[4] = { fb(s[kk][0]), fb(s[kk][2]), fb(s[kk][1]), fb(s[kk][3]) };
            const float* vrow = Vb + (kk * 8 + 2 * tg) * VSTR + g;
            #pragma unroll
            for (int ni = 0; ni < 16; ni++) {
                uint32_t b0 = fb(vrow[ni * 8]);
                uint32_t b1 = fb(vrow[VSTR + ni * 8]);
                mma8(o[ni], a, b0, b1);
            }
        }
        __syncthreads();
    }

    // epilogue
    float* Og = g_attn + ((size_t)bh * NSEQ + qt * 128) * HD2;
    #pragma unroll
    for (int half = 0; half < 2; half++) {
        float inv = 1.f / lrun[half];
        int r = wid * 16 + g + half * 8;
        #pragma unroll
        for (int ni = 0; ni < 16; ni++) {
            *(float2*)(Og + (size_t)r * HD2 + ni * 8 + tg * 2) =
                make_float2(o[ni][half * 2 + 0] * inv,
                            o[ni][half * 2 + 1] * inv);
        }
    }
}

// ---------------- combine: o0 - lam*o1, RMSNorm(128), *w*0.2, tf32-round ----
__global__ __launch_bounds__(128) void combine_kernel(const float* __restrict__ norm_w)
{
    int idx = blockIdx.x;
    int n   = idx & (NSEQ - 1);
    int be  = idx >> 11;
    int b_  = be >> 3, e = be & 7;
    int d   = threadIdx.x;
    float lam = g_lambda;

    size_t base0 = (((size_t)(b_ * NHEADS + 2 * e    )) * NSEQ + n) * HD2;
    size_t base1 = (((size_t)(b_ * NHEADS + 2 * e + 1)) * NSEQ + n) * HD2;
    float xv = g_attn[base0 + d] - lam * g_attn[base1 + d];

    float ss = xv * xv;
    #pragma unroll
    for (int off = 16; off > 0; off >>= 1)
        ss += __shfl_xor_sync(0xffffffffu, ss, off);
    __shared__ float red[4];
    if ((d & 31) == 0) red[d >> 5] = ss;
    __syncthreads();
    float tot = red[0] + red[1] + red[2] + red[3];
    float rms = rsqrtf(tot * (1.0f / HD2) + 1e-5f);

    g_comb[((size_t)(b_ * NSEQ + n)) * DIMC + e * HD2 + d] =
        f2tf(xv * rms * norm_w[d] * 0.2f);
}

// ---------------- launch -----------------------------------------------------
extern "C" void kernel_launch(void* const* d_in, const int* in_sizes, int n_in,
                              void* d_out, int out_size)
{
    const float* x      = (const float*)d_in[0];
    const float* Wq     = (const float*)d_in[1];
    const float* bq     = (const float*)d_in[2];
    const float* Wk     = (const float*)d_in[3];
    const float* bk     = (const float*)d_in[4];
    const float* Wv     = (const float*)d_in[5];
    const float* bv     = (const float*)d_in[6];
    const float* Wo     = (const float*)d_in[7];
    const float* bo     = (const float*)d_in[8];
    const float* norm_w = (const float*)d_in[9];
    const float* lq1    = (const float*)d_in[10];
    const float* lk1    = (const float*)d_in[11];
    const float* lq2    = (const float*)d_in[12];
    const float* lk2    = (const float*)d_in[13];
    float* out = (float*)d_out;

    lambda_kernel<<<1, 32>>>(lq1, lk1, lq2, lk2);

    float* xr = nullptr; cudaGetSymbolAddress((void**)&xr, g_xr);
    float* wr = nullptr; cudaGetSymbolAddress((void**)&wr, g_wr);
    round_kernel<<<MTOT * DIMC / 1024, 256>>>(x,  xr);
    round_kernel<<<DIMC * DIMC / 1024, 256>>>(Wq, wr + 0 * DIMC * DIMC);
    round_kernel<<<DIMC * DIMC / 1024, 256>>>(Wk, wr + 1 * DIMC * DIMC);
    round_kernel<<<DIMC * DIMC / 1024, 256>>>(Wv, wr + 2 * DIMC * DIMC);
    round_kernel<<<DIMC * DIMC / 1024, 256>>>(Wo, wr + 3 * DIMC * DIMC);

    int gemm_smem = 3 * 2 * SSTR * (int)sizeof(float);   // 110,592 B
    cudaFuncSetAttribute(gemm_mma_kernel, cudaFuncAttributeMaxDynamicSharedMemorySize, gemm_smem);

    dim3 gg(DIMC / 128, MTOT / 128);   // (8, 32)
    gemm_mma_kernel<<<gg, 256, gemm_smem>>>(xr, wr + 0 * DIMC * DIMC, bq, nullptr, 0);
    gemm_mma_kernel<<<gg, 256, gemm_smem>>>(xr, wr + 1 * DIMC * DIMC, bk, nullptr, 1);
    gemm_mma_kernel<<<gg, 256, gemm_smem>>>(xr, wr + 2 * DIMC * DIMC, bv, nullptr, 2);

    int flash_smem = (128 * 68 + 2 * 64 * 68 + 2 * 64 * VSTR) * (int)sizeof(float); // 141,312
    cudaFuncSetAttribute(flash_kernel, cudaFuncAttributeMaxDynamicSharedMemorySize, flash_smem);
    flash_kernel<<<dim3(NSEQ / 128, NB * NHEADS), 256, flash_smem>>>();

    combine_kernel<<<NB * NEFF * NSEQ, 128>>>(norm_w);

    gemm_mma_kernel<<<gg, 256, gemm_smem>>>(nullptr, wr + 3 * DIMC * DIMC, bo, out, 3);
}

// round 11
// speedup vs baseline: 2.2172x; 1.6579x over previous
#include <cuda_runtime.h>
#include <cuda_fp16.h>
#include <math.h>
#include <stdint.h>

#define DIMC   1024
#define NB     2
#define NSEQ   2048
#define NHEADS 16
#define NEFF   8
#define HDIM   64
#define HD2    128
#define MTOT   (NB*NSEQ)          // 4096
#define L2E    1.4426950408889634f

// ---------------- scratch (device globals; no allocations allowed) ----------
__device__ float  g_lambda;
__device__ __half g_xh[MTOT*DIMC];              // fp16 x
__device__ __half g_wh[4][DIMC*DIMC];           // fp16 Wq,Wk,Wv,Wo
__device__ __half g_qh[NB*NHEADS*NSEQ*HDIM];    // [b,h,n,hd] pre-scaled fp16
__device__ __half g_kh[NB*NHEADS*NSEQ*HDIM];    // [b,h,n,hd] fp16
__device__ __half g_vh[NB*NEFF*NSEQ*HD2];       // [b,e,n,128] fp16 natural
__device__ __half g_vt[NB*NEFF*HD2*NSEQ];       // [b,e,d,n]  fp16 transposed
__device__ float  g_attn[NB*NHEADS*NSEQ*HD2];   // per-head flash output (f32)
__device__ __half g_combh[MTOT*DIMC];           // combined+normed fp16

// ==================== helpers ======================
__device__ __forceinline__ uint32_t smem_u32(const void* p) {
    uint32_t a;
    asm("{ .reg .u64 t; cvta.to.shared.u64 t, %1; cvt.u32.u64 %0, t; }" : "=r"(a) : "l"(p));
    return a;
}
__device__ __forceinline__ uint32_t ldu32(const __half* p) { return *(const uint32_t*)p; }
__device__ __forceinline__ uint32_t packh2(float a, float b) {
    __half2 h = __floats2half2_rn(a, b);
    return *(uint32_t*)&h;
}

// m16n8k16 fp16 mma, fp32 accum: D += A(row) * B(col)
__device__ __forceinline__ void mma16(float* d, const uint32_t* a, uint32_t b0, uint32_t b1) {
    asm volatile("mma.sync.aligned.m16n8k16.row.col.f32.f16.f16.f32 "
                 "{%0,%1,%2,%3}, {%4,%5,%6,%7}, {%8,%9}, {%0,%1,%2,%3};"
                 : "+f"(d[0]), "+f"(d[1]), "+f"(d[2]), "+f"(d[3])
                 : "r"(a[0]), "r"(a[1]), "r"(a[2]), "r"(a[3]), "r"(b0), "r"(b1));
}

#define CP_ASYNC16(dst, src) \
    asm volatile("cp.async.cg.shared.global [%0], [%1], 16;" :: "r"(dst), "l"(src) : "memory")
#define CP_COMMIT() asm volatile("cp.async.commit_group;" ::: "memory")
#define CP_WAIT1()  asm volatile("cp.async.wait_group 1;" ::: "memory")
#define CP_WAIT2()  asm volatile("cp.async.wait_group 2;" ::: "memory")

// ---------------- fp16 pre-round: dst[i] = half(src[i]) ---------------------
__global__ __launch_bounds__(256) void round_kernel(const float* __restrict__ src,
                                                    __half* __restrict__ dst)
{
    int i = (blockIdx.x * 256 + threadIdx.x) * 4;
    float4 v = *(const float4*)(src + i);
    uint2 o;
    o.x = packh2(v.x, v.y);
    o.y = packh2(v.z, v.w);
    *(uint2*)(dst + i) = o;
}

// ---------------- lambda = exp(lq1.lk1) - exp(lq2.lk2) + 0.8 ----------------
__global__ void lambda_kernel(const float* __restrict__ lq1, const float* __restrict__ lk1,
                              const float* __restrict__ lq2, const float* __restrict__ lk2)
{
    int t = threadIdx.x;
    float s1 = 0.f, s2 = 0.f;
    for (int i = t; i < HDIM; i += 32) {
        s1 += lq1[i] * lk1[i];
        s2 += lq2[i] * lk2[i];
    }
    #pragma unroll
    for (int off = 16; off > 0; off >>= 1) {
        s1 += __shfl_xor_sync(0xffffffffu, s1, off);
        s2 += __shfl_xor_sync(0xffffffffu, s2, off);
    }
    if (t == 0) g_lambda = expf(s1) - expf(s2) + 0.8f;
}

// ---------------- V transpose: g_vh [be][n][128] -> g_vt [be][d][2048] ------
__global__ __launch_bounds__(256) void vtrans_kernel()
{
    __shared__ __half T[64][136];
    int be = blockIdx.y;
    int n0 = blockIdx.x * 64;
    const __half* src = g_vh + ((size_t)be * NSEQ + n0) * HD2;
    int tid = threadIdx.x;
    #pragma unroll
    for (int i = 0; i < 4; i++) {
        int id = tid + i * 256;
        int r = id >> 4, c8 = (id & 15) * 8;
        *(uint4*)&T[r][c8] = *(const uint4*)(src + (size_t)r * HD2 + c8);
    }
    __syncthreads();
    __half* dst = g_vt + (size_t)be * HD2 * NSEQ;
    #pragma unroll
    for (int i = 0; i < 16; i++) {
        int id = tid + i * 256;
        int d = id >> 5, h2 = id & 31;
        __half2 v = __halves2half2(T[2 * h2][d], T[2 * h2 + 1][d]);
        *(__half2*)(dst + (size_t)d * NSEQ + n0 + 2 * h2) = v;
    }
}

// ============ fp16 mma.sync GEMM NT, 4-stage cp.async, single-sync ==========
// 256 threads (8 warps), CTA 128x128, warp 32x64 (2m x 8n atoms), K-chunk 32.
// mode 0: g_qh (*0.125), 1: g_kh, 2: g_vh, 3: outp (f32)
#define SSH (128*40)       // halfs per matrix per stage (row stride 40)

__global__ __launch_bounds__(256, 2) void gemm_mma_kernel(const __half* __restrict__ A,
                                                          const __half* __restrict__ W,
                                                          const float* __restrict__ bias,
                                                          float* __restrict__ outp, int mode)
{
    extern __shared__ __half smh[];
    uint32_t sbase = smem_u32(smh);

    const __half* Ap = (mode == 3) ? g_combh : A;
    int m0 = blockIdx.y * 128;
    int n0 = blockIdx.x * 128;
    int tid = threadIdx.x, wid = tid >> 5, lane = tid & 31;
    int wm = wid >> 1, wn = wid & 1;
    int g = lane >> 2, tg = lane & 3;

    int lrow = tid >> 2;                  // 0..63 (row step 64)
    int lc16 = tid & 3;                   // 16B-chunk within row

    float acc[2][8][4];
    #pragma unroll
    for (int mi = 0; mi < 2; mi++)
        #pragma unroll
        for (int ni = 0; ni < 8; ni++)
            #pragma unroll
            for (int j = 0; j < 4; j++) acc[mi][ni][j] = 0.f;

    #define GEMM_ISSUE(c, st) do { \
        uint32_t as = sbase + (uint32_t)((st) * 2 * SSH) * 2u; \
        uint32_t bs = as + (uint32_t)SSH * 2u; \
        const __half* ag = Ap + (size_t)m0 * DIMC + (c) * 32; \
        const __half* bg = W  + (size_t)n0 * DIMC + (c) * 32; \
        _Pragma("unroll") \
        for (int i = 0; i < 2; i++) { \
            int row = lrow + i * 64; \
            CP_ASYNC16(as + (uint32_t)(row * 40 + lc16 * 8) * 2u, ag + (size_t)row * DIMC + lc16 * 8); \
            CP_ASYNC16(bs + (uint32_t)(row * 40 + lc16 * 8) * 2u, bg + (size_t)row * DIMC + lc16 * 8); \
        } \
    } while (0)

    GEMM_ISSUE(0, 0); CP_COMMIT();
    GEMM_ISSUE(1, 1); CP_COMMIT();
    GEMM_ISSUE(2, 2); CP_COMMIT();

    for (int c = 0; c < 32; c++) {
        int st = c & 3;
        CP_WAIT2();                 // group c complete (c+1, c+2 may be pending)
        __syncthreads();            // all warps finished compute(c-1); data c visible
        if (c + 3 < 32) GEMM_ISSUE(c + 3, (c + 3) & 3);
        CP_COMMIT();

        const __half* As = smh + st * 2 * SSH;
        const __half* Bs = As + SSH;
        #pragma unroll
        for (int kk = 0; kk < 2; kk++) {
            uint32_t a[2][4];
            #pragma unroll
            for (int mi = 0; mi < 2; mi++) {
                const __half* base = As + (wm * 32 + mi * 16 + g) * 40 + kk * 16 + 2 * tg;
                a[mi][0] = ldu32(base);
                a[mi][1] = ldu32(base + 8 * 40);
                a[mi][2] = ldu32(base + 8);
                a[mi][3] = ldu32(base + 8 * 40 + 8);
            }
            #pragma unroll
            for (int ni = 0; ni < 8; ni++) {
                const __half* bb = Bs + (wn * 64 + ni * 8 + g) * 40 + kk * 16 + 2 * tg;
                uint32_t b0 = ldu32(bb);
                uint32_t b1 = ldu32(bb + 8);
                mma16(acc[0][ni], a[0], b0, b1);
                mma16(acc[1][ni], a[1], b0, b1);
            }
        }
    }

    // epilogue: scatter with bias
    #pragma unroll
    for (int mi = 0; mi < 2; mi++) {
        int m = m0 + wm * 32 + mi * 16 + g;
        #pragma unroll
        for (int ni = 0; ni < 8; ni++) {
            int n = n0 + wn * 64 + ni * 8 + tg * 2;
            float2 bs2 = *(const float2*)(bias + n);
            #pragma unroll
            for (int half_ = 0; half_ < 2; half_++) {
                int mm = m + half_ * 8;
                float x = acc[mi][ni][half_ * 2 + 0] + bs2.x;
                float y = acc[mi][ni][half_ * 2 + 1] + bs2.y;
                int b_ = mm >> 11, nn = mm & 2047;
                if (mode == 0) {
                    int h = n >> 6, hd = n & 63;
                    *(uint32_t*)(g_qh + (((size_t)(b_*NHEADS+h))*NSEQ+nn)*HDIM + hd) =
                        packh2(x * 0.125f, y * 0.125f);
                } else if (mode == 1) {
                    int h = n >> 6, hd = n & 63;
                    *(uint32_t*)(g_kh + (((size_t)(b_*NHEADS+h))*NSEQ+nn)*HDIM + hd) =
                        packh2(x, y);
                } else if (mode == 2) {
                    int e = n >> 7, d2 = n & 127;
                    *(uint32_t*)(g_vh + (((size_t)(b_*NEFF+e))*NSEQ+nn)*HD2 + d2) =
                        packh2(x, y);
                } else {
                    *(float2*)(outp + (size_t)mm * DIMC + n) = make_float2(x, y);
                }
            }
        }
    }
}

// ---------------- flash attention, fp16 mma.sync, register-P ----------------
// Br=128, Bc=64, 256 threads = 8 warps x 16-row stripes.
// S mma m16n8k16 (4 kk); P packs directly into PV A-fragment (no smem P).
// V transposed fp16 smem [d][key] => PV B-frags contiguous half2 along k.
__global__ __launch_bounds__(256, 2) void flash_kernel()
{
    extern __shared__ __half sh[];
    __half* Qs = sh;                    // [128][72]
    __half* Ks = Qs + 128 * 72;         // [2][64][72]
    __half* Vs = Ks + 2 * 64 * 72;      // [2][128][72]  transposed [d][key]

    int qt = blockIdx.x;                // 0..15
    int bh = blockIdx.y;                // 0..31
    int b_ = bh >> 4, h = bh & 15, e = h >> 1;

    const __half* Qg = g_qh + ((size_t)bh * NSEQ + qt * 128) * HDIM;
    const __half* Kg = g_kh + (size_t)bh * NSEQ * HDIM;
    const __half* Vg = g_vt + ((size_t)(b_ * NEFF + e)) * HD2 * NSEQ;  // [d][n]

    int tid = threadIdx.x, wid = tid >> 5, lane = tid & 31;
    int g = lane >> 2, tg = lane & 3;
    uint32_t qbase = smem_u32(Qs);
    uint32_t kbase = smem_u32(Ks);
    uint32_t vbase = smem_u32(Vs);

    // ---- prologue: Q (group 0), K0+V0 (group 1)
    #pragma unroll
    for (int i = 0; i < 4; i++) {
        int id = tid + i * 256;
        int row = id >> 3, c8 = (id & 7) * 8;
        CP_ASYNC16(qbase + (uint32_t)(row * 72 + c8) * 2u, Qg + (size_t)row * HDIM + c8);
    }
    CP_COMMIT();
    #pragma unroll
    for (int i = 0; i < 2; i++) {
        int id = tid + i * 256;
        int row = id >> 3, c8 = (id & 7) * 8;
        CP_ASYNC16(kbase + (uint32_t)(row * 72 + c8) * 2u, Kg + (size_t)row * HDIM + c8);
    }
    #pragma unroll
    for (int i = 0; i < 4; i++) {
        int id = tid + i * 256;
        int row = id >> 3, c8 = (id & 7) * 8;       // row = d
        CP_ASYNC16(vbase + (uint32_t)(row * 72 + c8) * 2u, Vg + (size_t)row * NSEQ + c8);
    }
    CP_COMMIT();

    float o[16][4];
    #pragma unroll
    for (int ni = 0; ni < 16; ni++)
        #pragma unroll
        for (int j = 0; j < 4; j++) o[ni][j] = 0.f;
    float mrun[2] = {-1e30f, -1e30f};
    float lrun[2] = {0.f, 0.f};

    for (int kt = 0; kt < 32; kt++) {
        int buf = kt & 1;
        if (kt + 1 < 32) {
            uint32_t kb = kbase + (uint32_t)((buf ^ 1) * 64 * 72) * 2u;
            uint32_t vb = vbase + (uint32_t)((buf ^ 1) * 128 * 72) * 2u;
            #pragma unroll
            for (int i = 0; i < 2; i++) {
                int id = tid + i * 256;
                int row = id >> 3, c8 = (id & 7) * 8;
                CP_ASYNC16(kb + (uint32_t)(row * 72 + c8) * 2u,
                           Kg + (size_t)((kt + 1) * 64 + row) * HDIM + c8);
            }
            #pragma unroll
            for (int i = 0; i < 4; i++) {
                int id = tid + i * 256;
                int row = id >> 3, c8 = (id & 7) * 8;
                CP_ASYNC16(vb + (uint32_t)(row * 72 + c8) * 2u,
                           Vg + (size_t)row * NSEQ + (kt + 1) * 64 + c8);
            }
        }
        CP_COMMIT();
        CP_WAIT1();
        __syncthreads();

        // ---- S = Q K^T  (4 k16 steps)
        const __half* Kb = Ks + buf * 64 * 72;
        float s[8][4];
        #pragma unroll
        for (int ni = 0; ni < 8; ni++)
            #pragma unroll
            for (int j = 0; j < 4; j++) s[ni][j] = 0.f;
        #pragma unroll
        for (int kk = 0; kk < 4; kk++) {
            uint32_t a[4];
            const __half* qb = Qs + (wid * 16 + g) * 72 + kk * 16 + 2 * tg;
            a[0] = ldu32(qb);
            a[1] = ldu32(qb + 8 * 72);
            a[2] = ldu32(qb + 8);
            a[3] = ldu32(qb + 8 * 72 + 8);
            #pragma unroll
            for (int ni = 0; ni < 8; ni++) {
                const __half* bb = Kb + (ni * 8 + g) * 72 + kk * 16 + 2 * tg;
                uint32_t b0 = ldu32(bb);
                uint32_t b1 = ldu32(bb + 8);
                mma16(s[ni], a, b0, b1);
            }
        }

        // ---- online softmax (half 0: row g; half 1: row g+8)
        #pragma unroll
        for (int half_ = 0; half_ < 2; half_++) {
            float mx = -1e30f;
            #pragma unroll
            for (int ni = 0; ni < 8; ni++) {
                mx = fmaxf(mx, s[ni][half_ * 2 + 0]);
                mx = fmaxf(mx, s[ni][half_ * 2 + 1]);
            }
            mx = fmaxf(mx, __shfl_xor_sync(0xffffffffu, mx, 1));
            mx = fmaxf(mx, __shfl_xor_sync(0xffffffffu, mx, 2));
            float mnew = fmaxf(mrun[half_], mx);
            float sum = 0.f;
            #pragma unroll
            for (int ni = 0; ni < 8; ni++) {
                float p0 = exp2f((s[ni][half_ * 2 + 0] - mnew) * L2E);
                float p1 = exp2f((s[ni][half_ * 2 + 1] - mnew) * L2E);
                s[ni][half_ * 2 + 0] = p0;
                s[ni][half_ * 2 + 1] = p1;
                sum += p0 + p1;
            }
            sum += __shfl_xor_sync(0xffffffffu, sum, 1);
            sum += __shfl_xor_sync(0xffffffffu, sum, 2);
            if (mnew > mrun[half_]) {
                float alpha = exp2f((mrun[half_] - mnew) * L2E);
                lrun[half_] = lrun[half_] * alpha + sum;
                mrun[half_] = mnew;
                #pragma unroll
                for (int ni = 0; ni < 16; ni++) {
                    o[ni][half_ * 2 + 0] *= alpha;
                    o[ni][half_ * 2 + 1] *= alpha;
                }
            } else {
                lrun[half_] += sum;
            }
        }

        // ---- O += P V : P packs straight into the m16n8k16 A-fragment.
        // kk-block j covers keys 16j..16j+15: a0=s[2j][0..1], a2=s[2j+1][0..1],
        // a1/a3 = row g+8 halves. B: transposed V, half2 contiguous along k.
        const __half* Vb = Vs + buf * 128 * 72;
        #pragma unroll
        for (int j = 0; j < 4; j++) {
            uint32_t a[4];
            a[0] = packh2(s[2*j][0],   s[2*j][1]);
            a[1] = packh2(s[2*j][2],   s[2*j][3]);
            a[2] = packh2(s[2*j+1][0], s[2*j+1][1]);
            a[3] = packh2(s[2*j+1][2], s[2*j+1][3]);
            #pragma unroll
            for (int ni = 0; ni < 16; ni++) {
                const __half* vb = Vb + (ni * 8 + g) * 72 + j * 16 + 2 * tg;
                uint32_t b0 = ldu32(vb);
                uint32_t b1 = ldu32(vb + 8);
                mma16(o[ni], a, b0, b1);
            }
        }
        __syncthreads();
    }

    // epilogue
    float* Og = g_attn + ((size_t)bh * NSEQ + qt * 128) * HD2;
    #pragma unroll
    for (int half_ = 0; half_ < 2; half_++) {
        float inv = 1.f / lrun[half_];
        int r = wid * 16 + g + half_ * 8;
        #pragma unroll
        for (int ni = 0; ni < 16; ni++) {
            *(float2*)(Og + (size_t)r * HD2 + ni * 8 + tg * 2) =
                make_float2(o[ni][half_ * 2 + 0] * inv,
                            o[ni][half_ * 2 + 1] * inv);
        }
    }
}

// ---------------- combine: o0 - lam*o1, RMSNorm(128), *w*0.2, fp16 out ------
__global__ __launch_bounds__(64) void combine_kernel(const float* __restrict__ norm_w)
{
    int idx = blockIdx.x;
    int n   = idx & (NSEQ - 1);
    int be  = idx >> 11;
    int b_  = be >> 3, e = be & 7;
    int d2  = threadIdx.x;               // cols 2*d2, 2*d2+1
    float lam = g_lambda;

    size_t base0 = (((size_t)(b_ * NHEADS + 2 * e    )) * NSEQ + n) * HD2;
    size_t base1 = (((size_t)(b_ * NHEADS + 2 * e + 1)) * NSEQ + n) * HD2;
    float2 v0 = *(const float2*)(g_attn + base0 + 2 * d2);
    float2 v1 = *(const float2*)(g_attn + base1 + 2 * d2);
    float x0 = v0.x - lam * v1.x;
    float x1 = v0.y - lam * v1.y;

    float ss = x0 * x0 + x1 * x1;
    #pragma unroll
    for (int off = 16; off > 0; off >>= 1)
        ss += __shfl_xor_sync(0xffffffffu, ss, off);
    __shared__ float red[2];
    if ((d2 & 31) == 0) red[d2 >> 5] = ss;
    __syncthreads();
    float tot = red[0] + red[1];
    float rms = rsqrtf(tot * (1.0f / HD2) + 1e-5f);

    float2 w2 = *(const float2*)(norm_w + 2 * d2);
    *(uint32_t*)(g_combh + ((size_t)(b_ * NSEQ + n)) * DIMC + e * HD2 + 2 * d2) =
        packh2(x0 * rms * w2.x * 0.2f, x1 * rms * w2.y * 0.2f);
}

// ---------------- launch -----------------------------------------------------
extern "C" void kernel_launch(void* const* d_in, const int* in_sizes, int n_in,
                              void* d_out, int out_size)
{
    const float* x      = (const float*)d_in[0];
    const float* Wq     = (const float*)d_in[1];
    const float* bq     = (const float*)d_in[2];
    const float* Wk     = (const float*)d_in[3];
    const float* bk     = (const float*)d_in[4];
    const float* Wv     = (const float*)d_in[5];
    const float* bv     = (const float*)d_in[6];
    const float* Wo     = (const float*)d_in[7];
    const float* bo     = (const float*)d_in[8];
    const float* norm_w = (const float*)d_in[9];
    const float* lq1    = (const float*)d_in[10];
    const float* lk1    = (const float*)d_in[11];
    const float* lq2    = (const float*)d_in[12];
    const float* lk2    = (const float*)d_in[13];
    float* out = (float*)d_out;

    lambda_kernel<<<1, 32>>>(lq1, lk1, lq2, lk2);

    __half* xh = nullptr; cudaGetSymbolAddress((void**)&xh, g_xh);
    __half* wh = nullptr; cudaGetSymbolAddress((void**)&wh, g_wh);
    round_kernel<<<MTOT * DIMC / 1024, 256>>>(x,  xh);
    round_kernel<<<DIMC * DIMC / 1024, 256>>>(Wq, wh + 0 * DIMC * DIMC);
    round_kernel<<<DIMC * DIMC / 1024, 256>>>(Wk, wh + 1 * DIMC * DIMC);
    round_kernel<<<DIMC * DIMC / 1024, 256>>>(Wv, wh + 2 * DIMC * DIMC);
    round_kernel<<<DIMC * DIMC / 1024, 256>>>(Wo, wh + 3 * DIMC * DIMC);

    int gemm_smem = 4 * 2 * SSH * (int)sizeof(__half);   // 81,920 B
    cudaFuncSetAttribute(gemm_mma_kernel, cudaFuncAttributeMaxDynamicSharedMemorySize, gemm_smem);

    dim3 gg(DIMC / 128, MTOT / 128);   // (8, 32)
    gemm_mma_kernel<<<gg, 256, gemm_smem>>>(xh, wh + 0 * DIMC * DIMC, bq, nullptr, 0);
    gemm_mma_kernel<<<gg, 256, gemm_smem>>>(xh, wh + 1 * DIMC * DIMC, bk, nullptr, 1);
    gemm_mma_kernel<<<gg, 256, gemm_smem>>>(xh, wh + 2 * DIMC * DIMC, bv, nullptr, 2);

    vtrans_kernel<<<dim3(NSEQ / 64, NB * NEFF), 256>>>();

    int flash_smem = (128 * 72 + 2 * 64 * 72 + 2 * 128 * 72) * (int)sizeof(__half); // 73,728 B
    cudaFuncSetAttribute(flash_kernel, cudaFuncAttributeMaxDynamicSharedMemorySize, flash_smem);
    flash_kernel<<<dim3(NSEQ / 128, NB * NHEADS), 256, flash_smem>>>();

    combine_kernel<<<NB * NEFF * NSEQ, 64>>>(norm_w);

    gemm_mma_kernel<<<gg, 256, gemm_smem>>>(nullptr, wh + 3 * DIMC * DIMC, bo, out, 3);
}

// round 12
// speedup vs baseline: 2.4362x; 1.0988x over previous
#include <cuda_runtime.h>
#include <cuda_fp16.h>
#include <math.h>
#include <stdint.h>

#define DIMC   1024
#define NB     2
#define NSEQ   2048
#define NHEADS 16
#define NEFF   8
#define HDIM   64
#define HD2    128
#define MTOT   (NB*NSEQ)          // 4096
#define L2E    1.4426950408889634f

// ---------------- scratch (device globals; no allocations allowed) ----------
__device__ float  g_lambda;
__device__ __half g_xh[MTOT*DIMC];              // fp16 x
__device__ __half g_wh[4][DIMC*DIMC];           // fp16 Wq,Wk,Wv,Wo
__device__ __half g_qh[NB*NHEADS*NSEQ*HDIM];    // [b,h,n,hd] pre-scaled fp16
__device__ __half g_kh[NB*NHEADS*NSEQ*HDIM];    // [b,h,n,hd] fp16
__device__ __half g_vh[NB*NEFF*NSEQ*HD2];       // [b,e,n,128] fp16 natural
__device__ __half g_vt[NB*NEFF*HD2*NSEQ];       // [b,e,d,n]  fp16 transposed
__device__ float  g_attn[NB*NHEADS*NSEQ*HD2];   // per-head flash output (f32)
__device__ __half g_combh[MTOT*DIMC];           // combined+normed fp16

// ==================== helpers ======================
__device__ __forceinline__ uint32_t smem_u32(const void* p) {
    uint32_t a;
    asm("{ .reg .u64 t; cvta.to.shared.u64 t, %1; cvt.u32.u64 %0, t; }" : "=r"(a) : "l"(p));
    return a;
}
__device__ __forceinline__ uint32_t packh2(float a, float b) {
    __half2 h = __floats2half2_rn(a, b);
    return *(uint32_t*)&h;
}

// m16n8k16 fp16 mma, fp32 accum: D += A(row) * B(col)
__device__ __forceinline__ void mma16(float* d, const uint32_t* a, uint32_t b0, uint32_t b1) {
    asm volatile("mma.sync.aligned.m16n8k16.row.col.f32.f16.f16.f32 "
                 "{%0,%1,%2,%3}, {%4,%5,%6,%7}, {%8,%9}, {%0,%1,%2,%3};"
                 : "+f"(d[0]), "+f"(d[1]), "+f"(d[2]), "+f"(d[3])
                 : "r"(a[0]), "r"(a[1]), "r"(a[2]), "r"(a[3]), "r"(b0), "r"(b1));
}

#define LDSM4(r0, r1, r2, r3, addr) \
    asm volatile("ldmatrix.sync.aligned.m8n8.x4.shared.b16 {%0,%1,%2,%3}, [%4];" \
                 : "=r"(r0), "=r"(r1), "=r"(r2), "=r"(r3) : "r"(addr))

#define CP_ASYNC16(dst, src) \
    asm volatile("cp.async.cg.shared.global [%0], [%1], 16;" :: "r"(dst), "l"(src) : "memory")
#define CP_COMMIT() asm volatile("cp.async.commit_group;" ::: "memory")
#define CP_WAIT1()  asm volatile("cp.async.wait_group 1;" ::: "memory")
#define CP_WAIT2()  asm volatile("cp.async.wait_group 2;" ::: "memory")

// ---------------- fp16 pre-round: dst[i] = half(src[i]) ---------------------
__global__ __launch_bounds__(256) void round_kernel(const float* __restrict__ src,
                                                    __half* __restrict__ dst)
{
    int i = (blockIdx.x * 256 + threadIdx.x) * 4;
    float4 v = *(const float4*)(src + i);
    uint2 o;
    o.x = packh2(v.x, v.y);
    o.y = packh2(v.z, v.w);
    *(uint2*)(dst + i) = o;
}

// ---------------- lambda = exp(lq1.lk1) - exp(lq2.lk2) + 0.8 ----------------
__global__ void lambda_kernel(const float* __restrict__ lq1, const float* __restrict__ lk1,
                              const float* __restrict__ lq2, const float* __restrict__ lk2)
{
    int t = threadIdx.x;
    float s1 = 0.f, s2 = 0.f;
    for (int i = t; i < HDIM; i += 32) {
        s1 += lq1[i] * lk1[i];
        s2 += lq2[i] * lk2[i];
    }
    #pragma unroll
    for (int off = 16; off > 0; off >>= 1) {
        s1 += __shfl_xor_sync(0xffffffffu, s1, off);
        s2 += __shfl_xor_sync(0xffffffffu, s2, off);
    }
    if (t == 0) g_lambda = expf(s1) - expf(s2) + 0.8f;
}

// ---------------- V transpose: g_vh [be][n][128] -> g_vt [be][d][2048] ------
__global__ __launch_bounds__(256) void vtrans_kernel()
{
    __shared__ __half T[64][136];
    int be = blockIdx.y;
    int n0 = blockIdx.x * 64;
    const __half* src = g_vh + ((size_t)be * NSEQ + n0) * HD2;
    int tid = threadIdx.x;
    #pragma unroll
    for (int i = 0; i < 4; i++) {
        int id = tid + i * 256;
        int r = id >> 4, c8 = (id & 15) * 8;
        *(uint4*)&T[r][c8] = *(const uint4*)(src + (size_t)r * HD2 + c8);
    }
    __syncthreads();
    __half* dst = g_vt + (size_t)be * HD2 * NSEQ;
    #pragma unroll
    for (int i = 0; i < 16; i++) {
        int id = tid + i * 256;
        int d = id >> 5, h2 = id & 31;
        __half2 v = __halves2half2(T[2 * h2][d], T[2 * h2 + 1][d]);
        *(__half2*)(dst + (size_t)d * NSEQ + n0 + 2 * h2) = v;
    }
}

// ============ fp16 mma.sync GEMM NT, 4-stage cp.async, ldmatrix =============
// 256 threads (8 warps), CTA 128x128, warp 32x64 (2m x 8n atoms), K-chunk 32.
#define SSH (128*40)       // halfs per matrix per stage (row stride 40)

__global__ __launch_bounds__(256, 2) void gemm_mma_kernel(const __half* __restrict__ A,
                                                          const __half* __restrict__ W,
                                                          const float* __restrict__ bias,
                                                          float* __restrict__ outp, int mode)
{
    extern __shared__ __half smh[];
    uint32_t sbase = smem_u32(smh);

    const __half* Ap = (mode == 3) ? g_combh : A;
    int m0 = blockIdx.y * 128;
    int n0 = blockIdx.x * 128;
    int tid = threadIdx.x, wid = tid >> 5, lane = tid & 31;
    int wm = wid >> 1, wn = wid & 1;
    int g = lane >> 2, tg = lane & 3;
    int lm = lane >> 3, lr = lane & 7;
    // ldmatrix lane->row/col mapping
    int a_r = (lm & 1) * 8 + lr, a_c = (lm >> 1) * 8;   // A-type (m-major pair first)
    int b_r = (lm >> 1) * 8 + lr, b_c = (lm & 1) * 8;   // B-type (k-col pair first)

    int lrow = tid >> 2;                  // 0..63 (row step 64)
    int lc16 = tid & 3;                   // 16B-chunk within row

    float acc[2][8][4];
    #pragma unroll
    for (int mi = 0; mi < 2; mi++)
        #pragma unroll
        for (int ni = 0; ni < 8; ni++)
            #pragma unroll
            for (int j = 0; j < 4; j++) acc[mi][ni][j] = 0.f;

    #define GEMM_ISSUE(c, st) do { \
        uint32_t as = sbase + (uint32_t)((st) * 2 * SSH) * 2u; \
        uint32_t bs = as + (uint32_t)SSH * 2u; \
        const __half* ag = Ap + (size_t)m0 * DIMC + (c) * 32; \
        const __half* bg = W  + (size_t)n0 * DIMC + (c) * 32; \
        _Pragma("unroll") \
        for (int i = 0; i < 2; i++) { \
            int row = lrow + i * 64; \
            CP_ASYNC16(as + (uint32_t)(row * 40 + lc16 * 8) * 2u, ag + (size_t)row * DIMC + lc16 * 8); \
            CP_ASYNC16(bs + (uint32_t)(row * 40 + lc16 * 8) * 2u, bg + (size_t)row * DIMC + lc16 * 8); \
        } \
    } while (0)

    GEMM_ISSUE(0, 0); CP_COMMIT();
    GEMM_ISSUE(1, 1); CP_COMMIT();
    GEMM_ISSUE(2, 2); CP_COMMIT();

    uint32_t a_base = (uint32_t)((wm * 32 + a_r) * 40 + a_c) * 2u;
    uint32_t b_base = (uint32_t)((wn * 64 + b_r) * 40 + b_c) * 2u + (uint32_t)SSH * 2u;

    for (int c = 0; c < 32; c++) {
        int st = c & 3;
        CP_WAIT2();
        __syncthreads();
        if (c + 3 < 32) GEMM_ISSUE(c + 3, (c + 3) & 3);
        CP_COMMIT();

        uint32_t stb = sbase + (uint32_t)(st * 2 * SSH) * 2u;
        #pragma unroll
        for (int kk = 0; kk < 2; kk++) {
            uint32_t a0[4], a1[4];
            LDSM4(a0[0], a0[1], a0[2], a0[3], stb + a_base + (uint32_t)(kk * 16) * 2u);
            LDSM4(a1[0], a1[1], a1[2], a1[3], stb + a_base + (uint32_t)(16 * 40 + kk * 16) * 2u);
            #pragma unroll
            for (int p = 0; p < 4; p++) {
                uint32_t b0, b1, b2, b3;
                LDSM4(b0, b1, b2, b3, stb + b_base + (uint32_t)(p * 16 * 40 + kk * 16) * 2u);
                mma16(acc[0][2*p],   a0, b0, b1);
                mma16(acc[0][2*p+1], a0, b2, b3);
                mma16(acc[1][2*p],   a1, b0, b1);
                mma16(acc[1][2*p+1], a1, b2, b3);
            }
        }
    }

    // epilogue: scatter with bias
    #pragma unroll
    for (int mi = 0; mi < 2; mi++) {
        int m = m0 + wm * 32 + mi * 16 + g;
        #pragma unroll
        for (int ni = 0; ni < 8; ni++) {
            int n = n0 + wn * 64 + ni * 8 + tg * 2;
            float2 bs2 = *(const float2*)(bias + n);
            #pragma unroll
            for (int half_ = 0; half_ < 2; half_++) {
                int mm = m + half_ * 8;
                float x = acc[mi][ni][half_ * 2 + 0] + bs2.x;
                float y = acc[mi][ni][half_ * 2 + 1] + bs2.y;
                int b_ = mm >> 11, nn = mm & 2047;
                if (mode == 0) {
                    int h = n >> 6, hd = n & 63;
                    *(uint32_t*)(g_qh + (((size_t)(b_*NHEADS+h))*NSEQ+nn)*HDIM + hd) =
                        packh2(x * 0.125f, y * 0.125f);
                } else if (mode == 1) {
                    int h = n >> 6, hd = n & 63;
                    *(uint32_t*)(g_kh + (((size_t)(b_*NHEADS+h))*NSEQ+nn)*HDIM + hd) =
                        packh2(x, y);
                } else if (mode == 2) {
                    int e = n >> 7, d2 = n & 127;
                    *(uint32_t*)(g_vh + (((size_t)(b_*NEFF+e))*NSEQ+nn)*HD2 + d2) =
                        packh2(x, y);
                } else {
                    *(float2*)(outp + (size_t)mm * DIMC + n) = make_float2(x, y);
                }
            }
        }
    }
    #undef GEMM_ISSUE
}

// ---------------- flash attention, fp16 mma, ldmatrix, register-P -----------
// Br=128, Bc=64, 256 threads = 8 warps x 16-row stripes.
// Q frags hoisted (ldmatrix once); K/V frags via ldmatrix.x4.
__global__ __launch_bounds__(256, 2) void flash_kernel()
{
    extern __shared__ __half sh[];
    __half* Qs = sh;                    // [128][72]
    __half* Ks = Qs + 128 * 72;         // [2][64][72]
    __half* Vs = Ks + 2 * 64 * 72;      // [2][128][72]  transposed [d][key]

    int qt = blockIdx.x;                // 0..15
    int bh = blockIdx.y;                // 0..31
    int b_ = bh >> 4, h = bh & 15, e = h >> 1;

    const __half* Qg = g_qh + ((size_t)bh * NSEQ + qt * 128) * HDIM;
    const __half* Kg = g_kh + (size_t)bh * NSEQ * HDIM;
    const __half* Vg = g_vt + ((size_t)(b_ * NEFF + e)) * HD2 * NSEQ;  // [d][n]

    int tid = threadIdx.x, wid = tid >> 5, lane = tid & 31;
    int g = lane >> 2, tg = lane & 3;
    int lm = lane >> 3, lr = lane & 7;
    int a_r = (lm & 1) * 8 + lr, a_c = (lm >> 1) * 8;
    int b_r = (lm >> 1) * 8 + lr, b_c = (lm & 1) * 8;
    uint32_t qbase = smem_u32(Qs);
    uint32_t kbase = smem_u32(Ks);
    uint32_t vbase = smem_u32(Vs);

    // ---- prologue: Q (group 0), K0+V0 (group 1)
    #pragma unroll
    for (int i = 0; i < 4; i++) {
        int id = tid + i * 256;
        int row = id >> 3, c8 = (id & 7) * 8;
        CP_ASYNC16(qbase + (uint32_t)(row * 72 + c8) * 2u, Qg + (size_t)row * HDIM + c8);
    }
    CP_COMMIT();
    #pragma unroll
    for (int i = 0; i < 2; i++) {
        int id = tid + i * 256;
        int row = id >> 3, c8 = (id & 7) * 8;
        CP_ASYNC16(kbase + (uint32_t)(row * 72 + c8) * 2u, Kg + (size_t)row * HDIM + c8);
    }
    #pragma unroll
    for (int i = 0; i < 4; i++) {
        int id = tid + i * 256;
        int row = id >> 3, c8 = (id & 7) * 8;       // row = d
        CP_ASYNC16(vbase + (uint32_t)(row * 72 + c8) * 2u, Vg + (size_t)row * NSEQ + c8);
    }
    CP_COMMIT();
    CP_WAIT1();            // Q group done
    __syncthreads();

    // hoist Q fragments (kt-invariant) via ldmatrix
    uint32_t qf[4][4];
    uint32_t q_off = qbase + (uint32_t)((wid * 16 + a_r) * 72 + a_c) * 2u;
    #pragma unroll
    for (int kk = 0; kk < 4; kk++)
        LDSM4(qf[kk][0], qf[kk][1], qf[kk][2], qf[kk][3], q_off + (uint32_t)(kk * 16) * 2u);

    uint32_t kf_off = (uint32_t)(b_r * 72 + b_c) * 2u;   // + buf base + p*16*72*2 + kk*32

    float o[16][4];
    #pragma unroll
    for (int ni = 0; ni < 16; ni++)
        #pragma unroll
        for (int j = 0; j < 4; j++) o[ni][j] = 0.f;
    float mrun[2] = {-1e30f, -1e30f};
    float lrun[2] = {0.f, 0.f};

    for (int kt = 0; kt < 32; kt++) {
        int buf = kt & 1;
        if (kt + 1 < 32) {
            uint32_t kb = kbase + (uint32_t)((buf ^ 1) * 64 * 72) * 2u;
            uint32_t vb = vbase + (uint32_t)((buf ^ 1) * 128 * 72) * 2u;
            #pragma unroll
            for (int i = 0; i < 2; i++) {
                int id = tid + i * 256;
                int row = id >> 3, c8 = (id & 7) * 8;
                CP_ASYNC16(kb + (uint32_t)(row * 72 + c8) * 2u,
                           Kg + (size_t)((kt + 1) * 64 + row) * HDIM + c8);
            }
            #pragma unroll
            for (int i = 0; i < 4; i++) {
                int id = tid + i * 256;
                int row = id >> 3, c8 = (id & 7) * 8;
                CP_ASYNC16(vb + (uint32_t)(row * 72 + c8) * 2u,
                           Vg + (size_t)row * NSEQ + (kt + 1) * 64 + c8);
            }
        }
        CP_COMMIT();
        CP_WAIT1();
        __syncthreads();

        // ---- S = Q K^T  (ldmatrix B: 4 x4 per kk covering 64 keys)
        uint32_t Kb = kbase + (uint32_t)(buf * 64 * 72) * 2u + kf_off;
        float s[8][4];
        #pragma unroll
        for (int ni = 0; ni < 8; ni++)
            #pragma unroll
            for (int j = 0; j < 4; j++) s[ni][j] = 0.f;
        #pragma unroll
        for (int kk = 0; kk < 4; kk++) {
            #pragma unroll
            for (int p = 0; p < 4; p++) {
                uint32_t b0, b1, b2, b3;
                LDSM4(b0, b1, b2, b3, Kb + (uint32_t)(p * 16 * 72 + kk * 16) * 2u);
                mma16(s[2*p],   qf[kk], b0, b1);
                mma16(s[2*p+1], qf[kk], b2, b3);
            }
        }

        // ---- online softmax (half 0: row g; half 1: row g+8)
        #pragma unroll
        for (int half_ = 0; half_ < 2; half_++) {
            float mx = -1e30f;
            #pragma unroll
            for (int ni = 0; ni < 8; ni++) {
                mx = fmaxf(mx, s[ni][half_ * 2 + 0]);
                mx = fmaxf(mx, s[ni][half_ * 2 + 1]);
            }
            mx = fmaxf(mx, __shfl_xor_sync(0xffffffffu, mx, 1));
            mx = fmaxf(mx, __shfl_xor_sync(0xffffffffu, mx, 2));
            float mnew = fmaxf(mrun[half_], mx);
            float sum = 0.f;
            #pragma unroll
            for (int ni = 0; ni < 8; ni++) {
                float p0 = exp2f((s[ni][half_ * 2 + 0] - mnew) * L2E);
                float p1 = exp2f((s[ni][half_ * 2 + 1] - mnew) * L2E);
                s[ni][half_ * 2 + 0] = p0;
                s[ni][half_ * 2 + 1] = p1;
                sum += p0 + p1;
            }
            sum += __shfl_xor_sync(0xffffffffu, sum, 1);
            sum += __shfl_xor_sync(0xffffffffu, sum, 2);
            if (mnew > mrun[half_]) {
                float alpha = exp2f((mrun[half_] - mnew) * L2E);
                lrun[half_] = lrun[half_] * alpha + sum;
                mrun[half_] = mnew;
                #pragma unroll
                for (int ni = 0; ni < 16; ni++) {
                    o[ni][half_ * 2 + 0] *= alpha;
                    o[ni][half_ * 2 + 1] *= alpha;
                }
            } else {
                lrun[half_] += sum;
            }
        }

        // ---- O += P V : P packs straight into the m16n8k16 A-fragment.
        uint32_t Vb = vbase + (uint32_t)(buf * 128 * 72) * 2u + kf_off;
        #pragma unroll
        for (int j = 0; j < 4; j++) {
            uint32_t a[4];
            a[0] = packh2(s[2*j][0],   s[2*j][1]);
            a[1] = packh2(s[2*j][2],   s[2*j][3]);
            a[2] = packh2(s[2*j+1][0], s[2*j+1][1]);
            a[3] = packh2(s[2*j+1][2], s[2*j+1][3]);
            #pragma unroll
            for (int vp = 0; vp < 8; vp++) {
                uint32_t b0, b1, b2, b3;
                LDSM4(b0, b1, b2, b3, Vb + (uint32_t)(vp * 16 * 72 + j * 16) * 2u);
                mma16(o[2*vp],   a, b0, b1);
                mma16(o[2*vp+1], a, b2, b3);
            }
        }
        __syncthreads();
    }

    // epilogue
    float* Og = g_attn + ((size_t)bh * NSEQ + qt * 128) * HD2;
    #pragma unroll
    for (int half_ = 0; half_ < 2; half_++) {
        float inv = 1.f / lrun[half_];
        int r = wid * 16 + g + half_ * 8;
        #pragma unroll
        for (int ni = 0; ni < 16; ni++) {
            *(float2*)(Og + (size_t)r * HD2 + ni * 8 + tg * 2) =
                make_float2(o[ni][half_ * 2 + 0] * inv,
                            o[ni][half_ * 2 + 1] * inv);
        }
    }
}

// ---------------- combine: o0 - lam*o1, RMSNorm(128), *w*0.2, fp16 out ------
__global__ __launch_bounds__(64) void combine_kernel(const float* __restrict__ norm_w)
{
    int idx = blockIdx.x;
    int n   = idx & (NSEQ - 1);
    int be  = idx >> 11;
    int b_  = be >> 3, e = be & 7;
    int d2  = threadIdx.x;               // cols 2*d2, 2*d2+1
    float lam = g_lambda;

    size_t base0 = (((size_t)(b_ * NHEADS + 2 * e    )) * NSEQ + n) * HD2;
    size_t base1 = (((size_t)(b_ * NHEADS + 2 * e + 1)) * NSEQ + n) * HD2;
    float2 v0 = *(const float2*)(g_attn + base0 + 2 * d2);
    float2 v1 = *(const float2*)(g_attn + base1 + 2 * d2);
    float x0 = v0.x - lam * v1.x;
    float x1 = v0.y - lam * v1.y;

    float ss = x0 * x0 + x1 * x1;
    #pragma unroll
    for (int off = 16; off > 0; off >>= 1)
        ss += __shfl_xor_sync(0xffffffffu, ss, off);
    __shared__ float red[2];
    if ((d2 & 31) == 0) red[d2 >> 5] = ss;
    __syncthreads();
    float tot = red[0] + red[1];
    float rms = rsqrtf(tot * (1.0f / HD2) + 1e-5f);

    float2 w2 = *(const float2*)(norm_w + 2 * d2);
    *(uint32_t*)(g_combh + ((size_t)(b_ * NSEQ + n)) * DIMC + e * HD2 + 2 * d2) =
        packh2(x0 * rms * w2.x * 0.2f, x1 * rms * w2.y * 0.2f);
}

// ---------------- launch -----------------------------------------------------
extern "C" void kernel_launch(void* const* d_in, const int* in_sizes, int n_in,
                              void* d_out, int out_size)
{
    const float* x      = (const float*)d_in[0];
    const float* Wq     = (const float*)d_in[1];
    const float* bq     = (const float*)d_in[2];
    const float* Wk     = (const float*)d_in[3];
    const float* bk     = (const float*)d_in[4];
    const float* Wv     = (const float*)d_in[5];
    const float* bv     = (const float*)d_in[6];
    const float* Wo     = (const float*)d_in[7];
    const float* bo     = (const float*)d_in[8];
    const float* norm_w = (const float*)d_in[9];
    const float* lq1    = (const float*)d_in[10];
    const float* lk1    = (const float*)d_in[11];
    const float* lq2    = (const float*)d_in[12];
    const float* lk2    = (const float*)d_in[13];
    float* out = (float*)d_out;

    lambda_kernel<<<1, 32>>>(lq1, lk1, lq2, lk2);

    __half* xh = nullptr; cudaGetSymbolAddress((void**)&xh, g_xh);
    __half* wh = nullptr; cudaGetSymbolAddress((void**)&wh, g_wh);
    round_kernel<<<MTOT * DIMC / 1024, 256>>>(x,  xh);
    round_kernel<<<DIMC * DIMC / 1024, 256>>>(Wq, wh + 0 * DIMC * DIMC);
    round_kernel<<<DIMC * DIMC / 1024, 256>>>(Wk, wh + 1 * DIMC * DIMC);
    round_kernel<<<DIMC * DIMC / 1024, 256>>>(Wv, wh + 2 * DIMC * DIMC);
    round_kernel<<<DIMC * DIMC / 1024, 256>>>(Wo, wh + 3 * DIMC * DIMC);

    int gemm_smem = 4 * 2 * SSH * (int)sizeof(__half);   // 81,920 B
    cudaFuncSetAttribute(gemm_mma_kernel, cudaFuncAttributeMaxDynamicSharedMemorySize, gemm_smem);

    dim3 gg(DIMC / 128, MTOT / 128);   // (8, 32)
    gemm_mma_kernel<<<gg, 256, gemm_smem>>>(xh, wh + 0 * DIMC * DIMC, bq, nullptr, 0);
    gemm_mma_kernel<<<gg, 256, gemm_smem>>>(xh, wh + 1 * DIMC * DIMC, bk, nullptr, 1);
    gemm_mma_kernel<<<gg, 256, gemm_smem>>>(xh, wh + 2 * DIMC * DIMC, bv, nullptr, 2);

    vtrans_kernel<<<dim3(NSEQ / 64, NB * NEFF), 256>>>();

    int flash_smem = (128 * 72 + 2 * 64 * 72 + 2 * 128 * 72) * (int)sizeof(__half); // 73,728 B
    cudaFuncSetAttribute(flash_kernel, cudaFuncAttributeMaxDynamicSharedMemorySize, flash_smem);
    flash_kernel<<<dim3(NSEQ / 128, NB * NHEADS), 256, flash_smem>>>();

    combine_kernel<<<NB * NEFF * NSEQ, 64>>>(norm_w);

    gemm_mma_kernel<<<gg, 256, gemm_smem>>>(nullptr, wh + 3 * DIMC * DIMC, bo, out, 3);
}

// round 13
// speedup vs baseline: 2.6076x; 1.0704x over previous
#include <cuda_runtime.h>
#include <cuda_fp16.h>
#include <math.h>
#include <stdint.h>

#define DIMC   1024
#define NB     2
#define NSEQ   2048
#define NHEADS 16
#define NEFF   8
#define HDIM   64
#define HD2    128
#define MTOT   (NB*NSEQ)          // 4096
#define L2E    1.4426950408889634f

// ---------------- scratch (device globals; no allocations allowed) ----------
__device__ float  g_lambda;
__device__ __half g_xh[MTOT*DIMC];              // fp16 x
__device__ __half g_wh[4][DIMC*DIMC];           // fp16 Wq,Wk,Wv,Wo
__device__ __half g_qh[NB*NHEADS*NSEQ*HDIM];    // [b,h,n,hd] pre-scaled fp16
__device__ __half g_kh[NB*NHEADS*NSEQ*HDIM];    // [b,h,n,hd] fp16
__device__ __half g_vh[NB*NEFF*NSEQ*HD2];       // [b,e,n,128] fp16 natural
__device__ __half g_vt[NB*NEFF*HD2*NSEQ];       // [b,e,d,n]  fp16 transposed
__device__ __half g_combh[MTOT*DIMC];           // combined+normed fp16

// ==================== helpers ======================
__device__ __forceinline__ uint32_t smem_u32(const void* p) {
    uint32_t a;
    asm("{ .reg .u64 t; cvta.to.shared.u64 t, %1; cvt.u32.u64 %0, t; }" : "=r"(a) : "l"(p));
    return a;
}
__device__ __forceinline__ uint32_t packh2(float a, float b) {
    __half2 h = __floats2half2_rn(a, b);
    return *(uint32_t*)&h;
}

// m16n8k16 fp16 mma, fp32 accum: D += A(row) * B(col)
__device__ __forceinline__ void mma16(float* d, const uint32_t* a, uint32_t b0, uint32_t b1) {
    asm volatile("mma.sync.aligned.m16n8k16.row.col.f32.f16.f16.f32 "
                 "{%0,%1,%2,%3}, {%4,%5,%6,%7}, {%8,%9}, {%0,%1,%2,%3};"
                 : "+f"(d[0]), "+f"(d[1]), "+f"(d[2]), "+f"(d[3])
                 : "r"(a[0]), "r"(a[1]), "r"(a[2]), "r"(a[3]), "r"(b0), "r"(b1));
}

#define LDSM4(r0, r1, r2, r3, addr) \
    asm volatile("ldmatrix.sync.aligned.m8n8.x4.shared.b16 {%0,%1,%2,%3}, [%4];" \
                 : "=r"(r0), "=r"(r1), "=r"(r2), "=r"(r3) : "r"(addr))

#define CP_ASYNC16(dst, src) \
    asm volatile("cp.async.cg.shared.global [%0], [%1], 16;" :: "r"(dst), "l"(src) : "memory")
#define CP_COMMIT() asm volatile("cp.async.commit_group;" ::: "memory")
#define CP_WAIT1()  asm volatile("cp.async.wait_group 1;" ::: "memory")
#define CP_WAIT2()  asm volatile("cp.async.wait_group 2;" ::: "memory")

// ---------------- fp16 pre-round ------------------------
__global__ __launch_bounds__(256) void round_kernel(const float* __restrict__ src,
                                                    __half* __restrict__ dst)
{
    int i = (blockIdx.x * 256 + threadIdx.x) * 4;
    float4 v = *(const float4*)(src + i);
    uint2 o;
    o.x = packh2(v.x, v.y);
    o.y = packh2(v.z, v.w);
    *(uint2*)(dst + i) = o;
}

// fused: all four weight matrices in one launch (1024 blocks each)
__global__ __launch_bounds__(256) void round4_kernel(const float* __restrict__ s0,
                                                     const float* __restrict__ s1,
                                                     const float* __restrict__ s2,
                                                     const float* __restrict__ s3)
{
    int wsel = blockIdx.x >> 10;
    const float* src = (wsel == 0) ? s0 : (wsel == 1) ? s1 : (wsel == 2) ? s2 : s3;
    int i = ((blockIdx.x & 1023) * 256 + threadIdx.x) * 4;
    float4 v = *(const float4*)(src + i);
    uint2 o;
    o.x = packh2(v.x, v.y);
    o.y = packh2(v.z, v.w);
    *(uint2*)(&g_wh[wsel][0] + i) = o;
}

// ---------------- lambda = exp(lq1.lk1) - exp(lq2.lk2) + 0.8 ----------------
__global__ void lambda_kernel(const float* __restrict__ lq1, const float* __restrict__ lk1,
                              const float* __restrict__ lq2, const float* __restrict__ lk2)
{
    int t = threadIdx.x;
    float s1 = 0.f, s2 = 0.f;
    for (int i = t; i < HDIM; i += 32) {
        s1 += lq1[i] * lk1[i];
        s2 += lq2[i] * lk2[i];
    }
    #pragma unroll
    for (int off = 16; off > 0; off >>= 1) {
        s1 += __shfl_xor_sync(0xffffffffu, s1, off);
        s2 += __shfl_xor_sync(0xffffffffu, s2, off);
    }
    if (t == 0) g_lambda = expf(s1) - expf(s2) + 0.8f;
}

// ---------------- V transpose: g_vh [be][n][128] -> g_vt [be][d][2048] ------
__global__ __launch_bounds__(256) void vtrans_kernel()
{
    __shared__ __half T[64][136];
    int be = blockIdx.y;
    int n0 = blockIdx.x * 64;
    const __half* src = g_vh + ((size_t)be * NSEQ + n0) * HD2;
    int tid = threadIdx.x;
    #pragma unroll
    for (int i = 0; i < 4; i++) {
        int id = tid + i * 256;
        int r = id >> 4, c8 = (id & 15) * 8;
        *(uint4*)&T[r][c8] = *(const uint4*)(src + (size_t)r * HD2 + c8);
    }
    __syncthreads();
    __half* dst = g_vt + (size_t)be * HD2 * NSEQ;
    #pragma unroll
    for (int i = 0; i < 16; i++) {
        int id = tid + i * 256;
        int d = id >> 5, h2 = id & 31;
        __half2 v = __halves2half2(T[2 * h2][d], T[2 * h2 + 1][d]);
        *(__half2*)(dst + (size_t)d * NSEQ + n0 + 2 * h2) = v;
    }
}

// ============ fp16 mma.sync GEMM NT, 4-stage cp.async, ldmatrix =============
// 256 threads (8 warps), CTA 128x128, warp 32x64, K-chunk 32.
// fused=1: mode = blockIdx.z (0:Q,1:K,2:V), W = g_wh[mode].
// fused=0: mode=3 (output GEMM), W = Wp, bias = b0 (=bo), A = g_combh.
#define SSH (128*40)       // halfs per matrix per stage (row stride 40)

__global__ __launch_bounds__(256, 2) void gemm_mma_kernel(const __half* __restrict__ A,
                                                          const __half* __restrict__ Wp,
                                                          const float* __restrict__ b0,
                                                          const float* __restrict__ b1,
                                                          const float* __restrict__ b2,
                                                          float* __restrict__ outp, int fused)
{
    extern __shared__ __half smh[];
    uint32_t sbase = smem_u32(smh);

    int mode = fused ? (int)blockIdx.z : 3;
    const __half* W = fused ? &g_wh[mode][0] : Wp;
    const float* bias = (mode == 1) ? b1 : (mode == 2) ? b2 : b0;
    const __half* Ap = (mode == 3) ? g_combh : A;

    int m0 = blockIdx.y * 128;
    int n0 = blockIdx.x * 128;
    int tid = threadIdx.x, wid = tid >> 5, lane = tid & 31;
    int wm = wid >> 1, wn = wid & 1;
    int g = lane >> 2, tg = lane & 3;
    int lm = lane >> 3, lr = lane & 7;
    int a_r = (lm & 1) * 8 + lr, a_c = (lm >> 1) * 8;
    int b_r = (lm >> 1) * 8 + lr, b_c = (lm & 1) * 8;

    int lrow = tid >> 2;                  // 0..63 (row step 64)
    int lc16 = tid & 3;                   // 16B-chunk within row

    float acc[2][8][4];
    #pragma unroll
    for (int mi = 0; mi < 2; mi++)
        #pragma unroll
        for (int ni = 0; ni < 8; ni++)
            #pragma unroll
            for (int j = 0; j < 4; j++) acc[mi][ni][j] = 0.f;

    #define GEMM_ISSUE(c, st) do { \
        uint32_t as = sbase + (uint32_t)((st) * 2 * SSH) * 2u; \
        uint32_t bs = as + (uint32_t)SSH * 2u; \
        const __half* ag = Ap + (size_t)m0 * DIMC + (c) * 32; \
        const __half* bg = W  + (size_t)n0 * DIMC + (c) * 32; \
        _Pragma("unroll") \
        for (int i = 0; i < 2; i++) { \
            int row = lrow + i * 64; \
            CP_ASYNC16(as + (uint32_t)(row * 40 + lc16 * 8) * 2u, ag + (size_t)row * DIMC + lc16 * 8); \
            CP_ASYNC16(bs + (uint32_t)(row * 40 + lc16 * 8) * 2u, bg + (size_t)row * DIMC + lc16 * 8); \
        } \
    } while (0)

    GEMM_ISSUE(0, 0); CP_COMMIT();
    GEMM_ISSUE(1, 1); CP_COMMIT();
    GEMM_ISSUE(2, 2); CP_COMMIT();

    uint32_t a_base = (uint32_t)((wm * 32 + a_r) * 40 + a_c) * 2u;
    uint32_t b_base = (uint32_t)((wn * 64 + b_r) * 40 + b_c) * 2u + (uint32_t)SSH * 2u;

    for (int c = 0; c < 32; c++) {
        int st = c & 3;
        CP_WAIT2();
        __syncthreads();
        if (c + 3 < 32) GEMM_ISSUE(c + 3, (c + 3) & 3);
        CP_COMMIT();

        uint32_t stb = sbase + (uint32_t)(st * 2 * SSH) * 2u;
        #pragma unroll
        for (int kk = 0; kk < 2; kk++) {
            uint32_t a0[4], a1[4];
            LDSM4(a0[0], a0[1], a0[2], a0[3], stb + a_base + (uint32_t)(kk * 16) * 2u);
            LDSM4(a1[0], a1[1], a1[2], a1[3], stb + a_base + (uint32_t)(16 * 40 + kk * 16) * 2u);
            #pragma unroll
            for (int p = 0; p < 4; p++) {
                uint32_t b0r, b1r, b2r, b3r;
                LDSM4(b0r, b1r, b2r, b3r, stb + b_base + (uint32_t)(p * 16 * 40 + kk * 16) * 2u);
                mma16(acc[0][2*p],   a0, b0r, b1r);
                mma16(acc[0][2*p+1], a0, b2r, b3r);
                mma16(acc[1][2*p],   a1, b0r, b1r);
                mma16(acc[1][2*p+1], a1, b2r, b3r);
            }
        }
    }
    #undef GEMM_ISSUE

    // epilogue: scatter with bias
    #pragma unroll
    for (int mi = 0; mi < 2; mi++) {
        int m = m0 + wm * 32 + mi * 16 + g;
        #pragma unroll
        for (int ni = 0; ni < 8; ni++) {
            int n = n0 + wn * 64 + ni * 8 + tg * 2;
            float2 bs2 = *(const float2*)(bias + n);
            #pragma unroll
            for (int half_ = 0; half_ < 2; half_++) {
                int mm = m + half_ * 8;
                float x = acc[mi][ni][half_ * 2 + 0] + bs2.x;
                float y = acc[mi][ni][half_ * 2 + 1] + bs2.y;
                int b_ = mm >> 11, nn = mm & 2047;
                if (mode == 0) {
                    int h = n >> 6, hd = n & 63;
                    *(uint32_t*)(g_qh + (((size_t)(b_*NHEADS+h))*NSEQ+nn)*HDIM + hd) =
                        packh2(x * 0.125f, y * 0.125f);
                } else if (mode == 1) {
                    int h = n >> 6, hd = n & 63;
                    *(uint32_t*)(g_kh + (((size_t)(b_*NHEADS+h))*NSEQ+nn)*HDIM + hd) =
                        packh2(x, y);
                } else if (mode == 2) {
                    int e = n >> 7, d2 = n & 127;
                    *(uint32_t*)(g_vh + (((size_t)(b_*NEFF+e))*NSEQ+nn)*HD2 + d2) =
                        packh2(x, y);
                } else {
                    *(float2*)(outp + (size_t)mm * DIMC + n) = make_float2(x, y);
                }
            }
        }
    }
}

// ---------------- paired-head flash attention (fused combine) ---------------
// 512 threads = 16 warps; warps 0-7 head 2e, warps 8-15 head 2e+1;
// both heads share the V tile. Epilogue: diff, RMSNorm, write g_combh fp16.
__global__ __launch_bounds__(512, 1) void flash_kernel(const float* __restrict__ norm_w)
{
    extern __shared__ __half sh[];
    __half* Qs = sh;                    // [2 head][128][72]
    __half* Ks = Qs + 2 * 128 * 72;     // [2 buf][2 head][64][72]
    __half* Vs = Ks + 2 * 2 * 64 * 72;  // [2 buf][128][72]  transposed [d][key]
    float*  Os = (float*)Ks;            // epilogue overlay [128][132] f32

    int qt = blockIdx.x;                // 0..15
    int be = blockIdx.y;                // 0..15
    int b_ = be >> 3, e = be & 7;
    int bh0 = b_ * NHEADS + 2 * e;

    const __half* Qg = g_qh + ((size_t)bh0 * NSEQ + qt * 128) * HDIM;
    const __half* Kg = g_kh + (size_t)bh0 * NSEQ * HDIM;   // two heads contiguous
    const __half* Vg = g_vt + ((size_t)(b_ * NEFF + e)) * HD2 * NSEQ;  // [d][n]

    int tid = threadIdx.x, wid = tid >> 5, lane = tid & 31;
    int hs = wid >> 3, w8 = wid & 7;
    int g = lane >> 2, tg = lane & 3;
    int lm = lane >> 3, lr = lane & 7;
    int a_r = (lm & 1) * 8 + lr, a_c = (lm >> 1) * 8;
    int b_r = (lm >> 1) * 8 + lr, b_c = (lm & 1) * 8;
    uint32_t qbase = smem_u32(Qs);
    uint32_t kbase = smem_u32(Ks);
    uint32_t vbase = smem_u32(Vs);

    // ---- prologue: Q both heads (group 0)
    #pragma unroll
    for (int i = 0; i < 4; i++) {
        int id = tid + i * 512;
        int head = id >> 10, rem = id & 1023;
        int row = rem >> 3, c8 = (rem & 7) * 8;
        CP_ASYNC16(qbase + (uint32_t)((head * 128 + row) * 72 + c8) * 2u,
                   Qg + (size_t)head * NSEQ * HDIM + (size_t)row * HDIM + c8);
    }
    CP_COMMIT();
    // K0 both heads + V0 (group 1)
    #pragma unroll
    for (int i = 0; i < 2; i++) {
        int id = tid + i * 512;
        int head = id >> 9, rem = id & 511;
        int key = rem >> 3, c8 = (rem & 7) * 8;
        CP_ASYNC16(kbase + (uint32_t)((head * 64 + key) * 72 + c8) * 2u,
                   Kg + (size_t)head * NSEQ * HDIM + (size_t)key * HDIM + c8);
    }
    #pragma unroll
    for (int i = 0; i < 2; i++) {
        int id = tid + i * 512;
        int row = id >> 3, c8 = (id & 7) * 8;       // row = d
        CP_ASYNC16(vbase + (uint32_t)(row * 72 + c8) * 2u, Vg + (size_t)row * NSEQ + c8);
    }
    CP_COMMIT();
    CP_WAIT1();            // Q group done
    __syncthreads();

    // hoist Q fragments (kt-invariant)
    uint32_t qf[4][4];
    uint32_t q_off = qbase + (uint32_t)((hs * 128 + w8 * 16 + a_r) * 72 + a_c) * 2u;
    #pragma unroll
    for (int kk = 0; kk < 4; kk++)
        LDSM4(qf[kk][0], qf[kk][1], qf[kk][2], qf[kk][3], q_off + (uint32_t)(kk * 16) * 2u);

    uint32_t kf_off = (uint32_t)(b_r * 72 + b_c) * 2u;

    float o[16][4];
    #pragma unroll
    for (int ni = 0; ni < 16; ni++)
        #pragma unroll
        for (int j = 0; j < 4; j++) o[ni][j] = 0.f;
    float mrun[2] = {-1e30f, -1e30f};
    float lrun[2] = {0.f, 0.f};

    for (int kt = 0; kt < 32; kt++) {
        int buf = kt & 1;
        if (kt + 1 < 32) {
            uint32_t kb = kbase + (uint32_t)((buf ^ 1) * 2 * 64 * 72) * 2u;
            uint32_t vb = vbase + (uint32_t)((buf ^ 1) * 128 * 72) * 2u;
            #pragma unroll
            for (int i = 0; i < 2; i++) {
                int id = tid + i * 512;
                int head = id >> 9, rem = id & 511;
                int key = rem >> 3, c8 = (rem & 7) * 8;
                CP_ASYNC16(kb + (uint32_t)((head * 64 + key) * 72 + c8) * 2u,
                           Kg + (size_t)head * NSEQ * HDIM +
                               (size_t)((kt + 1) * 64 + key) * HDIM + c8);
            }
            #pragma unroll
            for (int i = 0; i < 2; i++) {
                int id = tid + i * 512;
                int row = id >> 3, c8 = (id & 7) * 8;
                CP_ASYNC16(vb + (uint32_t)(row * 72 + c8) * 2u,
                           Vg + (size_t)row * NSEQ + (kt + 1) * 64 + c8);
            }
        }
        CP_COMMIT();
        CP_WAIT1();
        __syncthreads();

        // ---- S = Q K^T (own head's K region)
        uint32_t Kb = kbase + (uint32_t)((buf * 2 + hs) * 64 * 72) * 2u + kf_off;
        float s[8][4];
        #pragma unroll
        for (int ni = 0; ni < 8; ni++)
            #pragma unroll
            for (int j = 0; j < 4; j++) s[ni][j] = 0.f;
        #pragma unroll
        for (int kk = 0; kk < 4; kk++) {
            #pragma unroll
            for (int p = 0; p < 4; p++) {
                uint32_t b0, b1, b2, b3;
                LDSM4(b0, b1, b2, b3, Kb + (uint32_t)(p * 16 * 72 + kk * 16) * 2u);
                mma16(s[2*p],   qf[kk], b0, b1);
                mma16(s[2*p+1], qf[kk], b2, b3);
            }
        }

        // ---- online softmax (half 0: row g; half 1: row g+8)
        #pragma unroll
        for (int half_ = 0; half_ < 2; half_++) {
            float mx = -1e30f;
            #pragma unroll
            for (int ni = 0; ni < 8; ni++) {
                mx = fmaxf(mx, s[ni][half_ * 2 + 0]);
                mx = fmaxf(mx, s[ni][half_ * 2 + 1]);
            }
            mx = fmaxf(mx, __shfl_xor_sync(0xffffffffu, mx, 1));
            mx = fmaxf(mx, __shfl_xor_sync(0xffffffffu, mx, 2));
            float mnew = fmaxf(mrun[half_], mx);
            float sum = 0.f;
            #pragma unroll
            for (int ni = 0; ni < 8; ni++) {
                float p0 = exp2f((s[ni][half_ * 2 + 0] - mnew) * L2E);
                float p1 = exp2f((s[ni][half_ * 2 + 1] - mnew) * L2E);
                s[ni][half_ * 2 + 0] = p0;
                s[ni][half_ * 2 + 1] = p1;
                sum += p0 + p1;
            }
            sum += __shfl_xor_sync(0xffffffffu, sum, 1);
            sum += __shfl_xor_sync(0xffffffffu, sum, 2);
            if (mnew > mrun[half_]) {
                float alpha = exp2f((mrun[half_] - mnew) * L2E);
                lrun[half_] = lrun[half_] * alpha + sum;
                mrun[half_] = mnew;
                #pragma unroll
                for (int ni = 0; ni < 16; ni++) {
                    o[ni][half_ * 2 + 0] *= alpha;
                    o[ni][half_ * 2 + 1] *= alpha;
                }
            } else {
                lrun[half_] += sum;
            }
        }

        // ---- O += P V (shared V; P packs straight into A-fragment)
        uint32_t Vb = vbase + (uint32_t)(buf * 128 * 72) * 2u + kf_off;
        #pragma unroll
        for (int j = 0; j < 4; j++) {
            uint32_t a[4];
            a[0] = packh2(s[2*j][0],   s[2*j][1]);
            a[1] = packh2(s[2*j][2],   s[2*j][3]);
            a[2] = packh2(s[2*j+1][0], s[2*j+1][1]);
            a[3] = packh2(s[2*j+1][2], s[2*j+1][3]);
            #pragma unroll
            for (int vp = 0; vp < 8; vp++) {
                uint32_t b0, b1, b2, b3;
                LDSM4(b0, b1, b2, b3, Vb + (uint32_t)(vp * 16 * 72 + j * 16) * 2u);
                mma16(o[2*vp],   a, b0, b1);
                mma16(o[2*vp+1], a, b2, b3);
            }
        }
        __syncthreads();
    }

    // ---- fused combine epilogue (K/V smem dead -> reuse as f32 stage) ------
    if (hs == 1) {                       // head 2e+1: stage normalized o1
        #pragma unroll
        for (int half_ = 0; half_ < 2; half_++) {
            float inv = 1.f / lrun[half_];
            int r = w8 * 16 + g + half_ * 8;
            #pragma unroll
            for (int ni = 0; ni < 16; ni++) {
                *(float2*)(Os + r * 132 + ni * 8 + tg * 2) =
                    make_float2(o[ni][half_ * 2 + 0] * inv,
                                o[ni][half_ * 2 + 1] * inv);
            }
        }
    }
    __syncthreads();
    if (hs == 0) {                       // head 2e: diff + RMSNorm + store
        float lam = g_lambda;
        #pragma unroll
        for (int half_ = 0; half_ < 2; half_++) {
            float inv = 1.f / lrun[half_];
            int r = w8 * 16 + g + half_ * 8;
            float ss = 0.f;
            #pragma unroll
            for (int ni = 0; ni < 16; ni++) {
                float2 o1v = *(const float2*)(Os + r * 132 + ni * 8 + tg * 2);
                float x0 = o[ni][half_ * 2 + 0] * inv - lam * o1v.x;
                float x1 = o[ni][half_ * 2 + 1] * inv - lam * o1v.y;
                o[ni][half_ * 2 + 0] = x0;
                o[ni][half_ * 2 + 1] = x1;
                ss += x0 * x0 + x1 * x1;
            }
            ss += __shfl_xor_sync(0xffffffffu, ss, 1);
            ss += __shfl_xor_sync(0xffffffffu, ss, 2);
            float rms = rsqrtf(ss * (1.0f / HD2) + 1e-5f);
            int n = qt * 128 + r;
            __half* dst = g_combh + ((size_t)(b_ * NSEQ + n)) * DIMC + e * HD2;
            #pragma unroll
            for (int ni = 0; ni < 16; ni++) {
                int col = ni * 8 + tg * 2;
                float2 w2 = *(const float2*)(norm_w + col);
                *(uint32_t*)(dst + col) =
                    packh2(o[ni][half_ * 2 + 0] * rms * w2.x * 0.2f,
                           o[ni][half_ * 2 + 1] * rms * w2.y * 0.2f);
            }
        }
    }
}

// ---------------- launch -----------------------------------------------------
extern "C" void kernel_launch(void* const* d_in, const int* in_sizes, int n_in,
                              void* d_out, int out_size)
{
    const float* x      = (const float*)d_in[0];
    const float* Wq     = (const float*)d_in[1];
    const float* bq     = (const float*)d_in[2];
    const float* Wk     = (const float*)d_in[3];
    const float* bk     = (const float*)d_in[4];
    const float* Wv     = (const float*)d_in[5];
    const float* bv     = (const float*)d_in[6];
    const float* Wo     = (const float*)d_in[7];
    const float* bo     = (const float*)d_in[8];
    const float* norm_w = (const float*)d_in[9];
    const float* lq1    = (const float*)d_in[10];
    const float* lk1    = (const float*)d_in[11];
    const float* lq2    = (const float*)d_in[12];
    const float* lk2    = (const float*)d_in[13];
    float* out = (float*)d_out;

    lambda_kernel<<<1, 32>>>(lq1, lk1, lq2, lk2);

    __half* xh = nullptr; cudaGetSymbolAddress((void**)&xh, g_xh);
    __half* wh = nullptr; cudaGetSymbolAddress((void**)&wh, g_wh);
    round_kernel<<<MTOT * DIMC / 1024, 256>>>(x, xh);
    round4_kernel<<<4 * DIMC * DIMC / 1024, 256>>>(Wq, Wk, Wv, Wo);

    int gemm_smem = 4 * 2 * SSH * (int)sizeof(__half);   // 81,920 B
    cudaFuncSetAttribute(gemm_mma_kernel, cudaFuncAttributeMaxDynamicSharedMemorySize, gemm_smem);

    // fused Q/K/V projections: blockIdx.z selects mode
    gemm_mma_kernel<<<dim3(DIMC / 128, MTOT / 128, 3), 256, gemm_smem>>>(
        xh, nullptr, bq, bk, bv, nullptr, 1);

    vtrans_kernel<<<dim3(NSEQ / 64, NB * NEFF), 256>>>();

    int flash_smem = (2 * 128 * 72 + 2 * 2 * 64 * 72 + 2 * 128 * 72) * (int)sizeof(__half); // 110,592
    cudaFuncSetAttribute(flash_kernel, cudaFuncAttributeMaxDynamicSharedMemorySize, flash_smem);
    flash_kernel<<<dim3(NSEQ / 128, NB * NEFF), 512, flash_smem>>>(norm_w);

    // output GEMM
    gemm_mma_kernel<<<dim3(DIMC / 128, MTOT / 128, 1), 256, gemm_smem>>>(
        nullptr, wh + 3 * DIMC * DIMC, bo, nullptr, nullptr, out, 0);
}